// round 4
// baseline (speedup 1.0000x reference)
#include <cuda_runtime.h>
#include <math.h>

#define B_ 16
#define N_ 196
#define C_ 512
#define T_ 20
#define D_ 128
#define S_ 38
#define NP_ 224                    // padded row/col stride for chain matrices
#define MP2_ (NP_*NP_)             // 50176 floats per padded matrix
#define QSIZE 8028160              // B*D*T*N
#define INV_TEMP (1.0f/0.07f)
#define EPS_ 1e-20f

// ---------------- scratch (static device globals; no allocation) ----------------
__device__ float g_qA[B_*T_*N_*D_];                  // [b][t][n][d] normalized q
__device__ float g_PH[(size_t)B_*S_*MP2_];           // transition mats, tf32-hi part
__device__ float g_PL[(size_t)B_*S_*MP2_];           // transition mats, tf32-lo part
__device__ float g_b1H[(size_t)B_*19*MP2_];
__device__ float g_b1L[(size_t)B_*19*MP2_];
__device__ float g_b2H[(size_t)B_*10*MP2_];
__device__ float g_b2L[(size_t)B_*10*MP2_];
__device__ float g_At[(size_t)B_*MP2_];              // final chain product (raw fp32)
__device__ float g_partial[2*B_];

__device__ __forceinline__ unsigned f2tf32(float x) {
  unsigned r;
  asm("cvt.rna.tf32.f32 %0, %1;" : "=r"(r) : "f"(x));
  return r;
}

// =============================================================================
// Kernel A: spatial pool + linear head + L2 normalize. (unchanged)
// =============================================================================
#define SMEM_A_BYTES ((C_*T_ + 64*D_ + 32) * sizeof(float))

__global__ __launch_bounds__(128) void kA(const float* __restrict__ maps,
                                          const float* __restrict__ W,
                                          const float* __restrict__ bias,
                                          float* __restrict__ qout) {
  extern __shared__ float sm[];
  float* qp    = sm;
  float* Ws    = sm + C_*T_;
  float* inorm = Ws + 64*D_;

  const int bn  = blockIdx.x;
  const int tid = threadIdx.x;

  const float4* src = reinterpret_cast<const float4*>(maps) + (size_t)bn * (C_*T_);
  for (int i = tid; i < C_*T_; i += 128) {
    float4 v = src[i];
    qp[i] = (v.x + v.y + v.z + v.w) * 0.25f;
  }
  __syncthreads();

  const int d0 = (tid & 31) * 4;
  const int t0 = (tid >> 5) * 5;
  float acc[4][5];
#pragma unroll
  for (int a = 0; a < 4; ++a)
#pragma unroll
    for (int t = 0; t < 5; ++t) acc[a][t] = 0.f;

  for (int cc = 0; cc < C_; cc += 64) {
    __syncthreads();
    const float4* wg  = reinterpret_cast<const float4*>(W + (size_t)cc * D_);
    float4*       ws4 = reinterpret_cast<float4*>(Ws);
    for (int j = tid; j < 64*D_/4; j += 128) ws4[j] = wg[j];
    __syncthreads();
#pragma unroll 4
    for (int k = 0; k < 64; ++k) {
      const int c = cc + k;
      float4 w = *reinterpret_cast<const float4*>(&Ws[k*D_ + d0]);
      float qv[5];
#pragma unroll
      for (int t = 0; t < 5; ++t) qv[t] = qp[c*T_ + t0 + t];
#pragma unroll
      for (int t = 0; t < 5; ++t) {
        acc[0][t] += w.x * qv[t];
        acc[1][t] += w.y * qv[t];
        acc[2][t] += w.z * qv[t];
        acc[3][t] += w.w * qv[t];
      }
    }
  }
  __syncthreads();

  float4 bv4 = *reinterpret_cast<const float4*>(bias + d0);
  float bvv[4] = {bv4.x, bv4.y, bv4.z, bv4.w};

  float part[5];
#pragma unroll
  for (int t = 0; t < 5; ++t) {
    float p = 0.f;
#pragma unroll
    for (int dd = 0; dd < 4; ++dd) {
      float yv = acc[dd][t] + bvv[dd];
      qp[(t0 + t)*D_ + (d0 + dd)] = yv;
      p += yv * yv;
    }
    part[t] = p;
  }
  float* red = Ws;
#pragma unroll
  for (int t = 0; t < 5; ++t) red[(t0 + t)*32 + (tid & 31)] = part[t];
  __syncthreads();

  if (tid < T_) {
    float ss = 0.f;
#pragma unroll
    for (int j = 0; j < 32; ++j) ss += red[tid*32 + j];
    inorm[tid] = 1.0f / fmaxf(sqrtf(ss), 1e-12f);
  }
  __syncthreads();

  const int b = bn / N_;
  const int n = bn % N_;
  for (int i = tid; i < T_*D_; i += 128) {
    const int t = i >> 7, d = i & 127;
    float v = qp[t*D_ + d] * inorm[t];
    g_qA[((size_t)(b*T_ + t)*N_ + n)*D_ + d] = v;
    qout[((size_t)(b*D_ + d)*T_ + t)*N_ + n] = v;
  }
}

// =============================================================================
// Kernel B: affinity + palindrome softmax -> padded split P (H/L, pad zeroed).
// =============================================================================
#define SMEM_B_BYTES ((N_*197 + 2*16*N_) * sizeof(float))

__global__ __launch_bounds__(392) void kB() {
  extern __shared__ float sm[];
  float* Sm = sm;                    // 196 x 197
  float* Qa = sm + N_*197;           // 16 x 196
  float* Qb = Qa + 16*N_;            // 16 x 196

  const int t   = blockIdx.x;
  const int b   = blockIdx.y;
  const int tid = threadIdx.x;
  const int ty  = tid / 14, tx = tid % 14;
  const int r0  = ty * 7,   c0 = tx * 14;

  const float* qa_base = g_qA + (size_t)((b*T_ + t    )*N_) * D_;
  const float* qb_base = g_qA + (size_t)((b*T_ + t + 1)*N_) * D_;

  float acc[7][14];
#pragma unroll
  for (int i = 0; i < 7; ++i)
#pragma unroll
    for (int j = 0; j < 14; ++j) acc[i][j] = 0.f;

  for (int k0 = 0; k0 < D_; k0 += 16) {
    __syncthreads();
    for (int idx = tid; idx < N_*16; idx += 392) {
      const int n = idx >> 4, k = idx & 15;
      Qa[k*N_ + n] = qa_base[(size_t)n*D_ + k0 + k];
      Qb[k*N_ + n] = qb_base[(size_t)n*D_ + k0 + k];
    }
    __syncthreads();
#pragma unroll
    for (int k = 0; k < 16; ++k) {
      float ra[7], rb[14];
#pragma unroll
      for (int i = 0; i < 7; ++i)  ra[i] = Qa[k*N_ + r0 + i];
#pragma unroll
      for (int j = 0; j < 14; ++j) rb[j] = Qb[k*N_ + c0 + j];
#pragma unroll
      for (int i = 0; i < 7; ++i)
#pragma unroll
        for (int j = 0; j < 14; ++j) acc[i][j] += ra[i] * rb[j];
    }
  }
  __syncthreads();

#pragma unroll
  for (int i = 0; i < 7; ++i)
#pragma unroll
    for (int j = 0; j < 14; ++j)
      Sm[(r0 + i)*197 + (c0 + j)] = acc[i][j] * INV_TEMP;
  __syncthreads();

  for (int idx = tid; idx < N_*N_; idx += 392) {
    const int rr = idx / N_, mm = idx - rr*N_;
    Sm[rr*197 + mm] = __expf(Sm[rr*197 + mm]);
  }
  __syncthreads();

  float* rinv = Qa;
  float* cinv = Qa + N_;
  if (tid < N_) {
    float rs = 0.f, cs = 0.f;
    for (int m = 0; m < N_; ++m) {
      rs += Sm[tid*197 + m];
      cs += Sm[m*197 + tid];
    }
    rinv[tid] = 1.0f / rs;
    cinv[tid] = 1.0f / cs;
  }
  __syncthreads();

  float* PfH = g_PH + (size_t)(b*S_ + t       )*MP2_;
  float* PfL = g_PL + (size_t)(b*S_ + t       )*MP2_;
  float* PbH = g_PH + (size_t)(b*S_ + (37 - t))*MP2_;
  float* PbL = g_PL + (size_t)(b*S_ + (37 - t))*MP2_;
  for (int idx = tid; idx < MP2_; idx += 392) {
    const int rr = idx / NP_, mm = idx - rr*NP_;
    float vf = 0.f, vb = 0.f;
    if (rr < N_ && mm < N_) {
      vf = Sm[rr*197 + mm] * rinv[rr];
      vb = Sm[mm*197 + rr] * cinv[rr];
    }
    unsigned hf = f2tf32(vf);
    unsigned hb = f2tf32(vb);
    PfH[idx] = __uint_as_float(hf);
    PfL[idx] = __uint_as_float(f2tf32(vf - __uint_as_float(hf)));
    PbH[idx] = __uint_as_float(hb);
    PbL[idx] = __uint_as_float(f2tf32(vb - __uint_as_float(hb)));
  }
}

// =============================================================================
// Kernel C v4: product-tree GEMM, mma.sync m16n8k8 tf32 fp32-split.
// Split precomputed in gmem (H/L arrays) -> NO cvt in mainloop.
// cp.async double-buffered K-chunks (KCH2=16). CTA = 224 rows x 56 cols,
// 7 warps, warp tile 32m x 56n (2 m-tiles x 7 n-tiles). Grid (4 ct, pairs, b).
// Conflict-free smem: A [m][k] stride 20, B [k][n] stride 72.
// =============================================================================
#define KCH2 16
#define ASTR 20
#define BSTR 72
#define A_FL (NP_*ASTR)                 // 4480 floats per A half
#define B_FL (KCH2*BSTR)                // 1152 floats per B half
#define AH_OFF 0
#define AL_OFF (A_FL)
#define BH_OFF (2*A_FL)
#define BL_OFF (2*A_FL + B_FL)
#define STAGE_FL (2*A_FL + 2*B_FL)      // 11264 floats per stage
#define SMEM_C_BYTES (2*STAGE_FL*sizeof(float))   // 90112 B

__device__ __forceinline__ void cpa16(float* dst_smem, const float* src) {
  unsigned d = (unsigned)__cvta_generic_to_shared(dst_smem);
  asm volatile("cp.async.cg.shared.global [%0], [%1], 16;\n" :: "r"(d), "l"(src));
}

__device__ __forceinline__ void mma_tf32(float* d, const unsigned* a,
                                         unsigned b0, unsigned b1) {
  asm volatile(
      "mma.sync.aligned.m16n8k8.row.col.f32.tf32.tf32.f32 "
      "{%0,%1,%2,%3}, {%4,%5,%6,%7}, {%8,%9}, {%0,%1,%2,%3};\n"
      : "+f"(d[0]), "+f"(d[1]), "+f"(d[2]), "+f"(d[3])
      : "r"(a[0]), "r"(a[1]), "r"(a[2]), "r"(a[3]), "r"(b0), "r"(b1));
}

__global__ __launch_bounds__(224, 2) void kC(int level, int Lin, int Lout, int npairs) {
  extern __shared__ float sm[];

  const float *srcH, *srcL; float *dstH, *dstL;
  switch (level) {
    case 0:  srcH = g_PH;  srcL = g_PL;  dstH = g_b1H; dstL = g_b1L; break;
    case 1:  srcH = g_b1H; srcL = g_b1L; dstH = g_b2H; dstL = g_b2L; break;
    case 2:  srcH = g_b2H; srcL = g_b2L; dstH = g_b1H; dstL = g_b1L; break;
    case 3:  srcH = g_b1H; srcL = g_b1L; dstH = g_b2H; dstL = g_b2L; break;
    case 4:  srcH = g_b2H; srcL = g_b2L; dstH = g_b1H; dstL = g_b1L; break;
    default: srcH = g_b1H; srcL = g_b1L; dstH = g_At;  dstL = 0;     break;
  }

  const int ct  = blockIdx.x;           // 0..3 column tiles of 56
  const int p   = blockIdx.y;
  const int b   = blockIdx.z;
  const int tid = threadIdx.x;

  if (p >= npairs) {                    // carry: copy H and L (levels < 5 only)
    const float4* SH = (const float4*)(srcH + ((size_t)b*Lin + (Lin - 1))*MP2_);
    const float4* SL = (const float4*)(srcL + ((size_t)b*Lin + (Lin - 1))*MP2_);
    float4* DH = (float4*)(dstH + ((size_t)b*Lout + npairs)*MP2_);
    float4* DL = (float4*)(dstL + ((size_t)b*Lout + npairs)*MP2_);
    const int q = MP2_/16;              // 3136 float4 per quarter
    for (int i = ct*q + tid; i < (ct + 1)*q; i += 224) { DH[i] = SH[i]; DL[i] = SL[i]; }
    return;
  }

  const float* AmH = srcH + ((size_t)b*Lin + 2*p + 1)*MP2_;
  const float* AmL = srcL + ((size_t)b*Lin + 2*p + 1)*MP2_;
  const float* BmH = srcH + ((size_t)b*Lin + 2*p    )*MP2_;
  const float* BmL = srcL + ((size_t)b*Lin + 2*p    )*MP2_;

  const int col0  = ct * 56;
  const int lane  = tid & 31;
  const int w     = tid >> 5;           // warp 0..6
  const int g     = lane >> 2;          // group id 0..7
  const int tig   = lane & 3;           // thread in group
  const int wbase = w * 32;             // warp row base

  float acc[2][7][4];
#pragma unroll
  for (int mt = 0; mt < 2; ++mt)
#pragma unroll
    for (int nt = 0; nt < 7; ++nt)
#pragma unroll
      for (int j = 0; j < 4; ++j) acc[mt][nt][j] = 0.f;

  auto fill = [&](int stg, int k0) {
    float* S = sm + stg*STAGE_FL;
#pragma unroll
    for (int i = 0; i < 4; ++i) {
      const int idx = tid + i*224;
      const int row = idx >> 2, seg = idx & 3;
      cpa16(S + AH_OFF + row*ASTR + seg*4, AmH + (size_t)row*NP_ + k0 + seg*4);
      cpa16(S + AL_OFF + row*ASTR + seg*4, AmL + (size_t)row*NP_ + k0 + seg*4);
    }
    {
      const int row = tid / 14, seg = tid - row*14;
      cpa16(S + BH_OFF + row*BSTR + seg*4, BmH + (size_t)(k0 + row)*NP_ + col0 + seg*4);
      cpa16(S + BL_OFF + row*BSTR + seg*4, BmL + (size_t)(k0 + row)*NP_ + col0 + seg*4);
    }
    asm volatile("cp.async.commit_group;\n" ::: "memory");
  };

  fill(0, 0);
  const int NCH = NP_ / KCH2;           // 14 chunks
  for (int c = 0; c < NCH; ++c) {
    if (c + 1 < NCH) {
      fill((c + 1) & 1, (c + 1)*KCH2);
      asm volatile("cp.async.wait_group 1;\n" ::: "memory");
    } else {
      asm volatile("cp.async.wait_group 0;\n" ::: "memory");
    }
    __syncthreads();

    const float* S   = sm + (c & 1)*STAGE_FL;
    const float* AsH = S + AH_OFF;
    const float* AsL = S + AL_OFF;
    const float* BsH = S + BH_OFF;
    const float* BsL = S + BL_OFF;

#pragma unroll
    for (int ks = 0; ks < 2; ++ks) {
      const int kb = ks*8;
      unsigned aH[2][4], aL[2][4];
#pragma unroll
      for (int mt = 0; mt < 2; ++mt) {
        const int mr = wbase + mt*16 + g;
        aH[mt][0] = __float_as_uint(AsH[ mr     *ASTR + kb + tig    ]);
        aH[mt][1] = __float_as_uint(AsH[(mr + 8)*ASTR + kb + tig    ]);
        aH[mt][2] = __float_as_uint(AsH[ mr     *ASTR + kb + tig + 4]);
        aH[mt][3] = __float_as_uint(AsH[(mr + 8)*ASTR + kb + tig + 4]);
        aL[mt][0] = __float_as_uint(AsL[ mr     *ASTR + kb + tig    ]);
        aL[mt][1] = __float_as_uint(AsL[(mr + 8)*ASTR + kb + tig    ]);
        aL[mt][2] = __float_as_uint(AsL[ mr     *ASTR + kb + tig + 4]);
        aL[mt][3] = __float_as_uint(AsL[(mr + 8)*ASTR + kb + tig + 4]);
      }
#pragma unroll
      for (int nt = 0; nt < 7; ++nt) {
        const int n = nt*8 + g;
        const unsigned bH0 = __float_as_uint(BsH[(kb + tig    )*BSTR + n]);
        const unsigned bH1 = __float_as_uint(BsH[(kb + tig + 4)*BSTR + n]);
        const unsigned bL0 = __float_as_uint(BsL[(kb + tig    )*BSTR + n]);
        const unsigned bL1 = __float_as_uint(BsL[(kb + tig + 4)*BSTR + n]);
#pragma unroll
        for (int mt = 0; mt < 2; ++mt) {
          mma_tf32(acc[mt][nt], aH[mt], bH0, bH1);
          mma_tf32(acc[mt][nt], aH[mt], bL0, bL1);
          mma_tf32(acc[mt][nt], aL[mt], bH0, bH1);
        }
      }
    }
    __syncthreads();
  }

  // ---- epilogue ----
  if (level < 5) {
    float* CH = dstH + ((size_t)b*Lout + p)*MP2_;
    float* CL = dstL + ((size_t)b*Lout + p)*MP2_;
#pragma unroll
    for (int mt = 0; mt < 2; ++mt) {
      const int r0 = wbase + mt*16 + g;
#pragma unroll
      for (int nt = 0; nt < 7; ++nt) {
        const int col = col0 + nt*8 + 2*tig;
        const float* a4 = acc[mt][nt];
        unsigned h0 = f2tf32(a4[0]), h1 = f2tf32(a4[1]);
        unsigned h2 = f2tf32(a4[2]), h3 = f2tf32(a4[3]);
        float l0 = a4[0] - __uint_as_float(h0), l1 = a4[1] - __uint_as_float(h1);
        float l2 = a4[2] - __uint_as_float(h2), l3 = a4[3] - __uint_as_float(h3);
        *(float2*)(CH + (size_t)r0*NP_ + col)       =
            make_float2(__uint_as_float(h0), __uint_as_float(h1));
        *(float2*)(CH + (size_t)(r0 + 8)*NP_ + col) =
            make_float2(__uint_as_float(h2), __uint_as_float(h3));
        *(float2*)(CL + (size_t)r0*NP_ + col)       =
            make_float2(__uint_as_float(f2tf32(l0)), __uint_as_float(f2tf32(l1)));
        *(float2*)(CL + (size_t)(r0 + 8)*NP_ + col) =
            make_float2(__uint_as_float(f2tf32(l2)), __uint_as_float(f2tf32(l3)));
      }
    }
  } else {
    float* Cm = g_At + (size_t)b*MP2_;
#pragma unroll
    for (int mt = 0; mt < 2; ++mt) {
      const int r0 = wbase + mt*16 + g;
#pragma unroll
      for (int nt = 0; nt < 7; ++nt) {
        const int col = col0 + nt*8 + 2*tig;
        const float* a4 = acc[mt][nt];
        *(float2*)(Cm + (size_t)r0*NP_ + col)       = make_float2(a4[0], a4[1]);
        *(float2*)(Cm + (size_t)(r0 + 8)*NP_ + col) = make_float2(a4[2], a4[3]);
      }
    }
  }
}

// =============================================================================
// Kernel D: per-row loss/acc from final At (g_At, stride 224).
// =============================================================================
__global__ void kD() {
  __shared__ float sl[N_], sa[N_];
  const int b = blockIdx.x, n = threadIdx.x;
  const float* row = g_At + (size_t)b*MP2_ + (size_t)n*NP_;
  float rs = 0.f, best = -1.f;
  int bi = 0;
  for (int m = 0; m < N_; ++m) {
    const float v = row[m];
    rs += v;
    if (v > best) { best = v; bi = m; }
  }
  const float diag = row[n];
  sl[n] = logf(rs + (float)N_ * EPS_) - logf(diag + EPS_);
  sa[n] = (bi == n) ? 1.f : 0.f;
  __syncthreads();
  if (n == 0) {
    float L = 0.f, A = 0.f;
    for (int i = 0; i < N_; ++i) { L += sl[i]; A += sa[i]; }
    g_partial[b]      = L;
    g_partial[B_ + b] = A;
  }
}

__global__ void kE(float* out, int out_size) {
  float L = 0.f, A = 0.f;
  for (int b = 0; b < B_; ++b) { L += g_partial[b]; A += g_partial[B_ + b]; }
  const float inv = 1.0f / (float)(B_ * N_);
  if (out_size > QSIZE)     out[QSIZE]     = L * inv;
  if (out_size > QSIZE + 1) out[QSIZE + 1] = A * inv;
}

// =============================================================================
extern "C" void kernel_launch(void* const* d_in, const int* in_sizes, int n_in,
                              void* d_out, int out_size) {
  const float* maps = (const float*)d_in[0];
  const float* W    = (const float*)d_in[1];
  const float* bias = (const float*)d_in[2];
  float* out = (float*)d_out;

  cudaFuncSetAttribute(kA, cudaFuncAttributeMaxDynamicSharedMemorySize, (int)SMEM_A_BYTES);
  cudaFuncSetAttribute(kB, cudaFuncAttributeMaxDynamicSharedMemorySize, (int)SMEM_B_BYTES);
  cudaFuncSetAttribute(kC, cudaFuncAttributeMaxDynamicSharedMemorySize, (int)SMEM_C_BYTES);

  kA<<<B_*N_, 128, SMEM_A_BYTES>>>(maps, W, bias, out);
  kB<<<dim3(T_ - 1, B_), 392, SMEM_B_BYTES>>>();

  // product tree: 38 -> 19 -> 10 -> 5 -> 3 -> 2 -> 1
  // {level, Lin, Lout, npairs, carry}
  const int lv[6][5] = {
    {0, 38, 19, 19, 0},
    {1, 19, 10,  9, 1},
    {2, 10,  5,  5, 0},
    {3,  5,  3,  2, 1},
    {4,  3,  2,  1, 1},
    {5,  2,  1,  1, 0},
  };
  for (int l = 0; l < 6; ++l) {
    kC<<<dim3(4, lv[l][3] + lv[l][4], B_), 224, SMEM_C_BYTES>>>(
        lv[l][0], lv[l][1], lv[l][2], lv[l][3]);
  }

  kD<<<B_, N_>>>();
  kE<<<1, 1>>>(out, out_size);
}

// round 5
// speedup vs baseline: 1.2533x; 1.2533x over previous
#include <cuda_runtime.h>
#include <cuda_bf16.h>
#include <math.h>

#define B_ 16
#define N_ 196
#define C_ 512
#define T_ 20
#define D_ 128
#define S_ 38
#define NP_ 224                    // padded row/col stride for chain matrices
#define MP2_ (NP_*NP_)             // 50176 elems per padded matrix
#define QSIZE 8028160              // B*D*T*N
#define INV_TEMP (1.0f/0.07f)
#define EPS_ 1e-20f

// ---------------- scratch (static device globals; no allocation) ----------------
__device__ float g_qA[B_*T_*N_*D_];                        // [b][t][n][d]
__device__ __nv_bfloat16 g_PH[(size_t)B_*S_*MP2_ + 256];   // transition mats hi
__device__ __nv_bfloat16 g_PL[(size_t)B_*S_*MP2_ + 256];   // transition mats lo
__device__ __nv_bfloat16 g_b1H[(size_t)B_*19*MP2_ + 256];
__device__ __nv_bfloat16 g_b1L[(size_t)B_*19*MP2_ + 256];
__device__ __nv_bfloat16 g_b2H[(size_t)B_*10*MP2_ + 256];
__device__ __nv_bfloat16 g_b2L[(size_t)B_*10*MP2_ + 256];
__device__ float g_At[(size_t)B_*MP2_];                    // final product fp32
__device__ float g_partial[2*B_];

// =============================================================================
// Kernel A: spatial pool + linear head + L2 normalize. (unchanged)
// =============================================================================
#define SMEM_A_BYTES ((C_*T_ + 64*D_ + 32) * sizeof(float))

__global__ __launch_bounds__(128) void kA(const float* __restrict__ maps,
                                          const float* __restrict__ W,
                                          const float* __restrict__ bias,
                                          float* __restrict__ qout) {
  extern __shared__ float sm[];
  float* qp    = sm;
  float* Ws    = sm + C_*T_;
  float* inorm = Ws + 64*D_;

  const int bn  = blockIdx.x;
  const int tid = threadIdx.x;

  const float4* src = reinterpret_cast<const float4*>(maps) + (size_t)bn * (C_*T_);
  for (int i = tid; i < C_*T_; i += 128) {
    float4 v = src[i];
    qp[i] = (v.x + v.y + v.z + v.w) * 0.25f;
  }
  __syncthreads();

  const int d0 = (tid & 31) * 4;
  const int t0 = (tid >> 5) * 5;
  float acc[4][5];
#pragma unroll
  for (int a = 0; a < 4; ++a)
#pragma unroll
    for (int t = 0; t < 5; ++t) acc[a][t] = 0.f;

  for (int cc = 0; cc < C_; cc += 64) {
    __syncthreads();
    const float4* wg  = reinterpret_cast<const float4*>(W + (size_t)cc * D_);
    float4*       ws4 = reinterpret_cast<float4*>(Ws);
    for (int j = tid; j < 64*D_/4; j += 128) ws4[j] = wg[j];
    __syncthreads();
#pragma unroll 4
    for (int k = 0; k < 64; ++k) {
      const int c = cc + k;
      float4 w = *reinterpret_cast<const float4*>(&Ws[k*D_ + d0]);
      float qv[5];
#pragma unroll
      for (int t = 0; t < 5; ++t) qv[t] = qp[c*T_ + t0 + t];
#pragma unroll
      for (int t = 0; t < 5; ++t) {
        acc[0][t] += w.x * qv[t];
        acc[1][t] += w.y * qv[t];
        acc[2][t] += w.z * qv[t];
        acc[3][t] += w.w * qv[t];
      }
    }
  }
  __syncthreads();

  float4 bv4 = *reinterpret_cast<const float4*>(bias + d0);
  float bvv[4] = {bv4.x, bv4.y, bv4.z, bv4.w};

  float part[5];
#pragma unroll
  for (int t = 0; t < 5; ++t) {
    float p = 0.f;
#pragma unroll
    for (int dd = 0; dd < 4; ++dd) {
      float yv = acc[dd][t] + bvv[dd];
      qp[(t0 + t)*D_ + (d0 + dd)] = yv;
      p += yv * yv;
    }
    part[t] = p;
  }
  float* red = Ws;
#pragma unroll
  for (int t = 0; t < 5; ++t) red[(t0 + t)*32 + (tid & 31)] = part[t];
  __syncthreads();

  if (tid < T_) {
    float ss = 0.f;
#pragma unroll
    for (int j = 0; j < 32; ++j) ss += red[tid*32 + j];
    inorm[tid] = 1.0f / fmaxf(sqrtf(ss), 1e-12f);
  }
  __syncthreads();

  const int b = bn / N_;
  const int n = bn % N_;
  for (int i = tid; i < T_*D_; i += 128) {
    const int t = i >> 7, d = i & 127;
    float v = qp[t*D_ + d] * inorm[t];
    g_qA[((size_t)(b*T_ + t)*N_ + n)*D_ + d] = v;
    qout[((size_t)(b*D_ + d)*T_ + t)*N_ + n] = v;
  }
}

// =============================================================================
// Kernel B: affinity + palindrome softmax -> bf16 hi/lo planes (pads zeroed).
// =============================================================================
#define SMEM_B_BYTES ((N_*197 + 2*16*N_) * sizeof(float))

__global__ __launch_bounds__(392) void kB() {
  extern __shared__ float sm[];
  float* Sm = sm;                    // 196 x 197
  float* Qa = sm + N_*197;           // 16 x 196
  float* Qb = Qa + 16*N_;            // 16 x 196

  const int t   = blockIdx.x;
  const int b   = blockIdx.y;
  const int tid = threadIdx.x;
  const int ty  = tid / 14, tx = tid % 14;
  const int r0  = ty * 7,   c0 = tx * 14;

  const float* qa_base = g_qA + (size_t)((b*T_ + t    )*N_) * D_;
  const float* qb_base = g_qA + (size_t)((b*T_ + t + 1)*N_) * D_;

  float acc[7][14];
#pragma unroll
  for (int i = 0; i < 7; ++i)
#pragma unroll
    for (int j = 0; j < 14; ++j) acc[i][j] = 0.f;

  for (int k0 = 0; k0 < D_; k0 += 16) {
    __syncthreads();
    for (int idx = tid; idx < N_*16; idx += 392) {
      const int n = idx >> 4, k = idx & 15;
      Qa[k*N_ + n] = qa_base[(size_t)n*D_ + k0 + k];
      Qb[k*N_ + n] = qb_base[(size_t)n*D_ + k0 + k];
    }
    __syncthreads();
#pragma unroll
    for (int k = 0; k < 16; ++k) {
      float ra[7], rb[14];
#pragma unroll
      for (int i = 0; i < 7; ++i)  ra[i] = Qa[k*N_ + r0 + i];
#pragma unroll
      for (int j = 0; j < 14; ++j) rb[j] = Qb[k*N_ + c0 + j];
#pragma unroll
      for (int i = 0; i < 7; ++i)
#pragma unroll
        for (int j = 0; j < 14; ++j) acc[i][j] += ra[i] * rb[j];
    }
  }
  __syncthreads();

#pragma unroll
  for (int i = 0; i < 7; ++i)
#pragma unroll
    for (int j = 0; j < 14; ++j)
      Sm[(r0 + i)*197 + (c0 + j)] = acc[i][j] * INV_TEMP;
  __syncthreads();

  for (int idx = tid; idx < N_*N_; idx += 392) {
    const int rr = idx / N_, mm = idx - rr*N_;
    Sm[rr*197 + mm] = __expf(Sm[rr*197 + mm]);
  }
  __syncthreads();

  float* rinv = Qa;
  float* cinv = Qa + N_;
  if (tid < N_) {
    float rs = 0.f, cs = 0.f;
    for (int m = 0; m < N_; ++m) {
      rs += Sm[tid*197 + m];
      cs += Sm[m*197 + tid];
    }
    rinv[tid] = 1.0f / rs;
    cinv[tid] = 1.0f / cs;
  }
  __syncthreads();

  __nv_bfloat16* PfH = g_PH + (size_t)(b*S_ + t       )*MP2_;
  __nv_bfloat16* PfL = g_PL + (size_t)(b*S_ + t       )*MP2_;
  __nv_bfloat16* PbH = g_PH + (size_t)(b*S_ + (37 - t))*MP2_;
  __nv_bfloat16* PbL = g_PL + (size_t)(b*S_ + (37 - t))*MP2_;
  for (int idx = tid; idx < MP2_; idx += 392) {
    const int rr = idx / NP_, mm = idx - rr*NP_;
    float vf = 0.f, vb = 0.f;
    if (rr < N_ && mm < N_) {
      vf = Sm[rr*197 + mm] * rinv[rr];
      vb = Sm[mm*197 + rr] * cinv[rr];
    }
    __nv_bfloat16 hf = __float2bfloat16_rn(vf);
    __nv_bfloat16 hb = __float2bfloat16_rn(vb);
    PfH[idx] = hf;
    PfL[idx] = __float2bfloat16_rn(vf - __bfloat162float(hf));
    PbH[idx] = hb;
    PbL[idx] = __float2bfloat16_rn(vb - __bfloat162float(hb));
  }
}

// =============================================================================
// Kernel C v5: product-tree GEMM, bf16 hi/lo split on mma.m16n8k16 + ldmatrix.
// C = src[2p+1] @ src[2p], 224^3.  CTA tile 112m x 56n, 224 thr (7 warps),
// warp = 16m x 56n (7 n-tiles, 28 acc regs). Grid (8 = 2mt x 4ct, pairs, b).
// Smem per stage: A 112 rows x 128B ([H k0..3 | L k0..3] 16B cols, XOR swizzle
// by row&7); B 32 k-rows x 256B ([H n0..7 | L n0..7], XOR swizzle by k&7).
// cp.async double-buffered, K-chunk 32.
// =============================================================================
#define ABYTES (112*128)
#define BBYTES (32*256)
#define STAGEB (ABYTES + BBYTES)            // 22528
#define SMEM_C_BYTES (2*STAGEB)             // 45056

__device__ __forceinline__ void cpa16(void* dst_smem, const void* src) {
  unsigned d = (unsigned)__cvta_generic_to_shared(dst_smem);
  asm volatile("cp.async.cg.shared.global [%0], [%1], 16;\n" :: "r"(d), "l"(src));
}
__device__ __forceinline__ unsigned smem_u32p(const void* p) {
  return (unsigned)__cvta_generic_to_shared(p);
}
__device__ __forceinline__ void ldsm4(unsigned addr, unsigned* r) {
  asm volatile("ldmatrix.sync.aligned.m8n8.x4.shared.b16 {%0,%1,%2,%3}, [%4];\n"
               : "=r"(r[0]), "=r"(r[1]), "=r"(r[2]), "=r"(r[3]) : "r"(addr));
}
__device__ __forceinline__ void ldsm4t(unsigned addr, unsigned* r) {
  asm volatile("ldmatrix.sync.aligned.m8n8.x4.trans.shared.b16 {%0,%1,%2,%3}, [%4];\n"
               : "=r"(r[0]), "=r"(r[1]), "=r"(r[2]), "=r"(r[3]) : "r"(addr));
}
__device__ __forceinline__ void ldsm2t(unsigned addr, unsigned* r) {
  asm volatile("ldmatrix.sync.aligned.m8n8.x2.trans.shared.b16 {%0,%1}, [%2];\n"
               : "=r"(r[0]), "=r"(r[1]) : "r"(addr));
}
__device__ __forceinline__ void mma_bf16(float* d, const unsigned* a,
                                         unsigned b0, unsigned b1) {
  asm volatile(
      "mma.sync.aligned.m16n8k16.row.col.f32.bf16.bf16.f32 "
      "{%0,%1,%2,%3}, {%4,%5,%6,%7}, {%8,%9}, {%0,%1,%2,%3};\n"
      : "+f"(d[0]), "+f"(d[1]), "+f"(d[2]), "+f"(d[3])
      : "r"(a[0]), "r"(a[1]), "r"(a[2]), "r"(a[3]), "r"(b0), "r"(b1));
}

__global__ __launch_bounds__(224, 3) void kC(int level, int Lin, int Lout, int npairs) {
  extern __shared__ char smc[];

  const __nv_bfloat16 *srcH, *srcL; __nv_bfloat16 *dstH, *dstL;
  switch (level) {
    case 0:  srcH = g_PH;  srcL = g_PL;  dstH = g_b1H; dstL = g_b1L; break;
    case 1:  srcH = g_b1H; srcL = g_b1L; dstH = g_b2H; dstL = g_b2L; break;
    case 2:  srcH = g_b2H; srcL = g_b2L; dstH = g_b1H; dstL = g_b1L; break;
    case 3:  srcH = g_b1H; srcL = g_b1L; dstH = g_b2H; dstL = g_b2L; break;
    case 4:  srcH = g_b2H; srcL = g_b2L; dstH = g_b1H; dstL = g_b1L; break;
    default: srcH = g_b1H; srcL = g_b1L; dstH = 0;     dstL = 0;     break;
  }

  const int xt  = blockIdx.x;            // 0..7: mt = xt&1, ct = xt>>1
  const int p   = blockIdx.y;
  const int b   = blockIdx.z;
  const int tid = threadIdx.x;

  if (p >= npairs) {                     // carry (levels < 5 only)
    const float4* SH = (const float4*)(srcH + ((size_t)b*Lin + (Lin - 1))*MP2_);
    const float4* SL = (const float4*)(srcL + ((size_t)b*Lin + (Lin - 1))*MP2_);
    float4* DH = (float4*)(dstH + ((size_t)b*Lout + npairs)*MP2_);
    float4* DL = (float4*)(dstL + ((size_t)b*Lout + npairs)*MP2_);
    const int q = MP2_*2/16/8;           // 784 float4 per x-tile per plane
    for (int i = xt*q + tid; i < (xt + 1)*q; i += 224) { DH[i] = SH[i]; DL[i] = SL[i]; }
    return;
  }

  const int mt = xt & 1, ct = xt >> 1;
  const int row0 = mt * 112;
  const int col0 = ct * 56;

  const char* AmH = (const char*)(srcH + ((size_t)b*Lin + 2*p + 1)*MP2_);
  const char* AmL = (const char*)(srcL + ((size_t)b*Lin + 2*p + 1)*MP2_);
  const char* BmH = (const char*)(srcH + ((size_t)b*Lin + 2*p    )*MP2_);
  const char* BmL = (const char*)(srcL + ((size_t)b*Lin + 2*p    )*MP2_);

  const int lane = tid & 31;
  const int w    = tid >> 5;             // warp 0..6
  const int tgrp = lane >> 3;            // ldmatrix address group 0..3
  const int g    = lane >> 2;            // mma group id
  const int tig  = lane & 3;

  // ldmatrix lane-address components
  const int arow = w*16 + (lane & 7) + (tgrp & 1)*8;     // A smem row 0..111
  const int ax   = arow & 7;
  const int bk   = (lane & 7) + (tgrp & 1)*8;            // B k within 16
  const int bk2  = ((lane & 15) & 7) + (((lane & 15) >> 3) & 1)*8;  // x2 variant

  float acc[7][4];
#pragma unroll
  for (int nt = 0; nt < 7; ++nt)
#pragma unroll
    for (int j = 0; j < 4; ++j) acc[nt][j] = 0.f;

  auto fill = [&](int stg, int k0) {
    char* S = smc + stg*STAGEB;
#pragma unroll
    for (int i = 0; i < 4; ++i) {
      const int idx = tid + i*224;
      const int r = idx >> 3, c = idx & 7;
      const int cw = c ^ (r & 7);
      const char* sp = (c < 4)
          ? (AmH + (size_t)(row0 + r)*448 + k0*2 + c*16)
          : (AmL + (size_t)(row0 + r)*448 + k0*2 + (c - 4)*16);
      cpa16(S + r*128 + cw*16, sp);
    }
    for (int idx = tid; idx < 512; idx += 224) {
      const int k = idx >> 4, c = idx & 15;
      int s7 = c & 7; if (s7 > 6) s7 = 6;          // clamp (n-pad to 64 unused)
      const int cw = c ^ (k & 7);
      const char* sp = ((c & 8) ? BmL : BmH) + (size_t)(k0 + k)*448 + col0*2 + s7*16;
      cpa16(S + ABYTES + k*256 + cw*16, sp);
    }
    asm volatile("cp.async.commit_group;\n" ::: "memory");
  };

  fill(0, 0);
  const int NCH = NP_ / 32;              // 7 chunks
  for (int c = 0; c < NCH; ++c) {
    if (c + 1 < NCH) {
      fill((c + 1) & 1, (c + 1)*32);
      asm volatile("cp.async.wait_group 1;\n" ::: "memory");
    } else {
      asm volatile("cp.async.wait_group 0;\n" ::: "memory");
    }
    __syncthreads();

    const char* S = smc + (c & 1)*STAGEB;
    const unsigned aBase = smem_u32p(S) + arow*128;
    const unsigned bBase = smem_u32p(S + ABYTES);

#pragma unroll
    for (int ks = 0; ks < 2; ++ks) {
      unsigned aH[4], aL[4];
      {
        const int ca = 2*ks + (tgrp >> 1);
        ldsm4(aBase + ((ca       ^ ax) << 4), aH);
        ldsm4(aBase + (((ca + 4) ^ ax) << 4), aL);
      }
      const int kk  = ks*16 + bk;
      const int ksw = kk & 7;
      const unsigned bRow = bBase + kk*256;
#pragma unroll
      for (int jp = 0; jp < 3; ++jp) {
        const int cH = 2*jp + (tgrp >> 1);
        unsigned bH[4], bL[4];
        ldsm4t(bRow + ((cH       ^ ksw) << 4), bH);
        ldsm4t(bRow + (((cH + 8) ^ ksw) << 4), bL);
        mma_bf16(acc[2*jp    ], aH, bH[0], bH[1]);
        mma_bf16(acc[2*jp    ], aH, bL[0], bL[1]);
        mma_bf16(acc[2*jp    ], aL, bH[0], bH[1]);
        mma_bf16(acc[2*jp + 1], aH, bH[2], bH[3]);
        mma_bf16(acc[2*jp + 1], aH, bL[2], bL[3]);
        mma_bf16(acc[2*jp + 1], aL, bH[2], bH[3]);
      }
      {   // n-tile 6 via x2.trans
        const int k2  = ks*16 + bk2;
        const unsigned bRow2 = bBase + k2*256;
        const int k2w = k2 & 7;
        unsigned bH[2], bL[2];
        ldsm2t(bRow2 + ((6  ^ k2w) << 4), bH);
        ldsm2t(bRow2 + ((14 ^ k2w) << 4), bL);
        mma_bf16(acc[6], aH, bH[0], bH[1]);
        mma_bf16(acc[6], aH, bL[0], bL[1]);
        mma_bf16(acc[6], aL, bH[0], bH[1]);
      }
    }
    __syncthreads();
  }

  // ---- epilogue ----
  const int r0g = row0 + w*16 + g;       // global rows r0g, r0g+8
  if (level < 5) {
    __nv_bfloat16* CH = dstH + ((size_t)b*Lout + p)*MP2_;
    __nv_bfloat16* CL = dstL + ((size_t)b*Lout + p)*MP2_;
#pragma unroll
    for (int nt = 0; nt < 7; ++nt) {
      const int col = col0 + nt*8 + 2*tig;
#pragma unroll
      for (int half = 0; half < 2; ++half) {
        const int r = r0g + half*8;
        const float x0 = acc[nt][2*half], x1 = acc[nt][2*half + 1];
        __nv_bfloat16 h0 = __float2bfloat16_rn(x0);
        __nv_bfloat16 h1 = __float2bfloat16_rn(x1);
        __nv_bfloat16 l0 = __float2bfloat16_rn(x0 - __bfloat162float(h0));
        __nv_bfloat16 l1 = __float2bfloat16_rn(x1 - __bfloat162float(h1));
        *(__nv_bfloat162*)(CH + (size_t)r*NP_ + col) = __nv_bfloat162(h0, h1);
        *(__nv_bfloat162*)(CL + (size_t)r*NP_ + col) = __nv_bfloat162(l0, l1);
      }
    }
  } else {
    float* Cm = g_At + (size_t)b*MP2_;
#pragma unroll
    for (int nt = 0; nt < 7; ++nt) {
      const int col = col0 + nt*8 + 2*tig;
      *(float2*)(Cm + (size_t)r0g*NP_ + col)       = make_float2(acc[nt][0], acc[nt][1]);
      *(float2*)(Cm + (size_t)(r0g + 8)*NP_ + col) = make_float2(acc[nt][2], acc[nt][3]);
    }
  }
}

// =============================================================================
// Kernel D: per-row loss/acc from final At (g_At, stride 224).
// =============================================================================
__global__ void kD() {
  __shared__ float sl[N_], sa[N_];
  const int b = blockIdx.x, n = threadIdx.x;
  const float* row = g_At + (size_t)b*MP2_ + (size_t)n*NP_;
  float rs = 0.f, best = -1.f;
  int bi = 0;
  for (int m = 0; m < N_; ++m) {
    const float v = row[m];
    rs += v;
    if (v > best) { best = v; bi = m; }
  }
  const float diag = row[n];
  sl[n] = logf(rs + (float)N_ * EPS_) - logf(diag + EPS_);
  sa[n] = (bi == n) ? 1.f : 0.f;
  __syncthreads();
  if (n == 0) {
    float L = 0.f, A = 0.f;
    for (int i = 0; i < N_; ++i) { L += sl[i]; A += sa[i]; }
    g_partial[b]      = L;
    g_partial[B_ + b] = A;
  }
}

__global__ void kE(float* out, int out_size) {
  float L = 0.f, A = 0.f;
  for (int b = 0; b < B_; ++b) { L += g_partial[b]; A += g_partial[B_ + b]; }
  const float inv = 1.0f / (float)(B_ * N_);
  if (out_size > QSIZE)     out[QSIZE]     = L * inv;
  if (out_size > QSIZE + 1) out[QSIZE + 1] = A * inv;
}

// =============================================================================
extern "C" void kernel_launch(void* const* d_in, const int* in_sizes, int n_in,
                              void* d_out, int out_size) {
  const float* maps = (const float*)d_in[0];
  const float* W    = (const float*)d_in[1];
  const float* bias = (const float*)d_in[2];
  float* out = (float*)d_out;

  cudaFuncSetAttribute(kA, cudaFuncAttributeMaxDynamicSharedMemorySize, (int)SMEM_A_BYTES);
  cudaFuncSetAttribute(kB, cudaFuncAttributeMaxDynamicSharedMemorySize, (int)SMEM_B_BYTES);
  cudaFuncSetAttribute(kC, cudaFuncAttributeMaxDynamicSharedMemorySize, (int)SMEM_C_BYTES);

  kA<<<B_*N_, 128, SMEM_A_BYTES>>>(maps, W, bias, out);
  kB<<<dim3(T_ - 1, B_), 392, SMEM_B_BYTES>>>();

  // product tree: 38 -> 19 -> 10 -> 5 -> 3 -> 2 -> 1
  // {level, Lin, Lout, npairs, carry}
  const int lv[6][5] = {
    {0, 38, 19, 19, 0},
    {1, 19, 10,  9, 1},
    {2, 10,  5,  5, 0},
    {3,  5,  3,  2, 1},
    {4,  3,  2,  1, 1},
    {5,  2,  1,  1, 0},
  };
  for (int l = 0; l < 6; ++l) {
    kC<<<dim3(8, lv[l][3] + lv[l][4], B_), 224, SMEM_C_BYTES>>>(
        lv[l][0], lv[l][1], lv[l][2], lv[l][3]);
  }

  kD<<<B_, N_>>>();
  kE<<<1, 1>>>(out, out_size);
}

// round 6
// speedup vs baseline: 2.2488x; 1.7943x over previous
#include <cuda_runtime.h>
#include <cuda_bf16.h>
#include <math.h>

#define B_ 16
#define N_ 196
#define C_ 512
#define T_ 20
#define D_ 128
#define S_ 38
#define NP_ 224                    // padded row/col stride for chain matrices
#define MP2_ (NP_*NP_)             // 50176 elems per padded matrix
#define QSIZE 8028160              // B*D*T*N
#define INV_TEMP (1.0f/0.07f)
#define EPS_ 1e-20f

// ---------------- scratch (static device globals; no allocation) ----------------
__device__ float g_qA[B_*T_*N_*D_];                                  // [b][t][n][d]
__device__ __align__(256) __nv_bfloat16 g_P [(size_t)B_*S_*MP2_ + 256];
__device__ __align__(256) __nv_bfloat16 g_b1[(size_t)B_*19*MP2_ + 256];
__device__ __align__(256) __nv_bfloat16 g_b2[(size_t)B_*10*MP2_ + 256];
__device__ float g_At[(size_t)B_*MP2_];                              // final product fp32
__device__ float g_partial[2*B_];

// ---------------- packed fp32x2 FMA helpers (bit-identical to 2x FFMA) -------
__device__ __forceinline__ unsigned long long pk2(float x, float y) {
  unsigned long long r;
  asm("mov.b64 %0, {%1,%2};" : "=l"(r) : "f"(x), "f"(y));
  return r;
}
__device__ __forceinline__ void fma2(unsigned long long& d,
                                     unsigned long long a, unsigned long long b) {
  asm("fma.rn.f32x2 %0, %1, %2, %0;" : "+l"(d) : "l"(a), "l"(b));
}
__device__ __forceinline__ float2 upk2(unsigned long long v) {
  float2 f;
  asm("mov.b64 {%0,%1}, %2;" : "=f"(f.x), "=f"(f.y) : "l"(v));
  return f;
}

// =============================================================================
// Kernel A: spatial pool + linear head + L2 normalize. (f32x2 packed FMA)
// =============================================================================
#define SMEM_A_BYTES ((C_*T_ + 64*D_ + 32) * sizeof(float))

__global__ __launch_bounds__(128) void kA(const float* __restrict__ maps,
                                          const float* __restrict__ W,
                                          const float* __restrict__ bias,
                                          float* __restrict__ qout) {
  extern __shared__ float sm[];
  float* qp    = sm;
  float* Ws    = sm + C_*T_;
  float* inorm = Ws + 64*D_;

  const int bn  = blockIdx.x;
  const int tid = threadIdx.x;

  const float4* src = reinterpret_cast<const float4*>(maps) + (size_t)bn * (C_*T_);
  for (int i = tid; i < C_*T_; i += 128) {
    float4 v = src[i];
    qp[i] = (v.x + v.y + v.z + v.w) * 0.25f;
  }
  __syncthreads();

  const int d0 = (tid & 31) * 4;
  const int t0 = (tid >> 5) * 5;
  unsigned long long acc2[2][5];
#pragma unroll
  for (int a = 0; a < 2; ++a)
#pragma unroll
    for (int t = 0; t < 5; ++t) acc2[a][t] = 0ULL;

  for (int cc = 0; cc < C_; cc += 64) {
    __syncthreads();
    const float4* wg  = reinterpret_cast<const float4*>(W + (size_t)cc * D_);
    float4*       ws4 = reinterpret_cast<float4*>(Ws);
    for (int j = tid; j < 64*D_/4; j += 128) ws4[j] = wg[j];
    __syncthreads();
#pragma unroll 4
    for (int k = 0; k < 64; ++k) {
      const int c = cc + k;
      float4 w = *reinterpret_cast<const float4*>(&Ws[k*D_ + d0]);
      unsigned long long w01 = pk2(w.x, w.y), w23 = pk2(w.z, w.w);
#pragma unroll
      for (int t = 0; t < 5; ++t) {
        const float qv = qp[c*T_ + t0 + t];
        const unsigned long long q2 = pk2(qv, qv);
        fma2(acc2[0][t], w01, q2);
        fma2(acc2[1][t], w23, q2);
      }
    }
  }
  __syncthreads();

  float4 bv4 = *reinterpret_cast<const float4*>(bias + d0);
  float bvv[4] = {bv4.x, bv4.y, bv4.z, bv4.w};

  float part[5];
#pragma unroll
  for (int t = 0; t < 5; ++t) {
    float2 lo = upk2(acc2[0][t]);
    float2 hi = upk2(acc2[1][t]);
    float ya[4] = {lo.x + bvv[0], lo.y + bvv[1], hi.x + bvv[2], hi.y + bvv[3]};
    float p = 0.f;
#pragma unroll
    for (int dd = 0; dd < 4; ++dd) {
      qp[(t0 + t)*D_ + (d0 + dd)] = ya[dd];
      p += ya[dd] * ya[dd];
    }
    part[t] = p;
  }
  float* red = Ws;
#pragma unroll
  for (int t = 0; t < 5; ++t) red[(t0 + t)*32 + (tid & 31)] = part[t];
  __syncthreads();

  if (tid < T_) {
    float ss = 0.f;
#pragma unroll
    for (int j = 0; j < 32; ++j) ss += red[tid*32 + j];
    inorm[tid] = 1.0f / fmaxf(sqrtf(ss), 1e-12f);
  }
  __syncthreads();

  const int b = bn / N_;
  const int n = bn % N_;
  for (int i = tid; i < T_*D_; i += 128) {
    const int t = i >> 7, d = i & 127;
    float v = qp[t*D_ + d] * inorm[t];
    g_qA[((size_t)(b*T_ + t)*N_ + n)*D_ + d] = v;
    qout[((size_t)(b*D_ + d)*T_ + t)*N_ + n] = v;
  }
}

// =============================================================================
// Kernel B: affinity + palindrome softmax -> bf16 P planes (pads zeroed).
// GEMM inner loop on packed f32x2.
// =============================================================================
#define SMEM_B_BYTES ((N_*197 + 2*16*N_) * sizeof(float))

__global__ __launch_bounds__(392) void kB() {
  extern __shared__ float sm[];
  float* Sm = sm;                    // 196 x 197
  float* Qa = sm + N_*197;           // 16 x 196
  float* Qb = Qa + 16*N_;            // 16 x 196

  const int t   = blockIdx.x;
  const int b   = blockIdx.y;
  const int tid = threadIdx.x;
  const int ty  = tid / 14, tx = tid % 14;
  const int r0  = ty * 7,   c0 = tx * 14;

  const float* qa_base = g_qA + (size_t)((b*T_ + t    )*N_) * D_;
  const float* qb_base = g_qA + (size_t)((b*T_ + t + 1)*N_) * D_;

  unsigned long long acc2[7][7];
#pragma unroll
  for (int i = 0; i < 7; ++i)
#pragma unroll
    for (int j = 0; j < 7; ++j) acc2[i][j] = 0ULL;

  for (int k0 = 0; k0 < D_; k0 += 16) {
    __syncthreads();
    for (int idx = tid; idx < N_*16; idx += 392) {
      const int n = idx >> 4, k = idx & 15;
      Qa[k*N_ + n] = qa_base[(size_t)n*D_ + k0 + k];
      Qb[k*N_ + n] = qb_base[(size_t)n*D_ + k0 + k];
    }
    __syncthreads();
#pragma unroll
    for (int k = 0; k < 16; ++k) {
      unsigned long long ra2[7], rb2[7];
#pragma unroll
      for (int i = 0; i < 7; ++i) {
        const float a = Qa[k*N_ + r0 + i];
        ra2[i] = pk2(a, a);
      }
#pragma unroll
      for (int j = 0; j < 7; ++j)
        rb2[j] = pk2(Qb[k*N_ + c0 + 2*j], Qb[k*N_ + c0 + 2*j + 1]);
#pragma unroll
      for (int i = 0; i < 7; ++i)
#pragma unroll
        for (int j = 0; j < 7; ++j) fma2(acc2[i][j], ra2[i], rb2[j]);
    }
  }
  __syncthreads();

#pragma unroll
  for (int i = 0; i < 7; ++i)
#pragma unroll
    for (int j = 0; j < 7; ++j) {
      float2 v = upk2(acc2[i][j]);
      Sm[(r0 + i)*197 + (c0 + 2*j)    ] = v.x * INV_TEMP;
      Sm[(r0 + i)*197 + (c0 + 2*j + 1)] = v.y * INV_TEMP;
    }
  __syncthreads();

  for (int idx = tid; idx < N_*N_; idx += 392) {
    const int rr = idx / N_, mm = idx - rr*N_;
    Sm[rr*197 + mm] = __expf(Sm[rr*197 + mm]);
  }
  __syncthreads();

  float* rinv = Qa;
  float* cinv = Qa + N_;
  if (tid < N_) {
    float rs = 0.f, cs = 0.f;
    for (int m = 0; m < N_; ++m) {
      rs += Sm[tid*197 + m];
      cs += Sm[m*197 + tid];
    }
    rinv[tid] = 1.0f / rs;
    cinv[tid] = 1.0f / cs;
  }
  __syncthreads();

  __nv_bfloat16* Pf = g_P + (size_t)(b*S_ + t       )*MP2_;
  __nv_bfloat16* Pb = g_P + (size_t)(b*S_ + (37 - t))*MP2_;
  for (int idx = tid; idx < MP2_/2; idx += 392) {
    const int rr = idx / 112;
    const int m2 = (idx - rr*112) * 2;
    float vf0 = 0.f, vf1 = 0.f, vb0 = 0.f, vb1 = 0.f;
    if (rr < N_ && m2 < N_) {
      vf0 = Sm[rr*197 + m2] * rinv[rr];
      vb0 = Sm[m2*197 + rr] * cinv[rr];
      if (m2 + 1 < N_) {
        vf1 = Sm[rr*197 + m2 + 1] * rinv[rr];
        vb1 = Sm[(m2 + 1)*197 + rr] * cinv[rr];
      }
    }
    *(__nv_bfloat162*)(Pf + (size_t)rr*NP_ + m2) =
        __nv_bfloat162(__float2bfloat16_rn(vf0), __float2bfloat16_rn(vf1));
    *(__nv_bfloat162*)(Pb + (size_t)rr*NP_ + m2) =
        __nv_bfloat162(__float2bfloat16_rn(vb0), __float2bfloat16_rn(vb1));
  }
}

// =============================================================================
// Kernel C v6: product-tree GEMM, pure bf16 mma.m16n8k16, whole-tile smem.
// C = src[2p+1] @ src[2p]. CTA tile 112m x 56n, 224 thr (7 warps),
// warp = 16m x 56n. K cropped to 208 (cols/rows 196..223 are exact zeros).
// Single cp.async fill of A(112x208) + B(208x64) -> 13 k-steps, no rechunking.
// Grid (8 = 2mt x 4ct, pairs[+carry], 16 b).
// =============================================================================
#define KS_ 13
#define AROWB 416                       // 26 x 16B (k 0..207)
#define ABYTES (112*AROWB)              // 46592
#define BROWB 128                       // 8 x 16B (n 0..63; 56 valid)
#define BBYTES (208*BROWB)              // 26624
#define SMEM_C_BYTES (ABYTES + BBYTES)  // 73216

__device__ __forceinline__ void cpa16(void* dst_smem, const void* src) {
  unsigned d = (unsigned)__cvta_generic_to_shared(dst_smem);
  asm volatile("cp.async.cg.shared.global [%0], [%1], 16;\n" :: "r"(d), "l"(src));
}
__device__ __forceinline__ unsigned smem_u32p(const void* p) {
  return (unsigned)__cvta_generic_to_shared(p);
}
__device__ __forceinline__ void ldsm4(unsigned addr, unsigned* r) {
  asm volatile("ldmatrix.sync.aligned.m8n8.x4.shared.b16 {%0,%1,%2,%3}, [%4];\n"
               : "=r"(r[0]), "=r"(r[1]), "=r"(r[2]), "=r"(r[3]) : "r"(addr));
}
__device__ __forceinline__ void ldsm4t(unsigned addr, unsigned* r) {
  asm volatile("ldmatrix.sync.aligned.m8n8.x4.trans.shared.b16 {%0,%1,%2,%3}, [%4];\n"
               : "=r"(r[0]), "=r"(r[1]), "=r"(r[2]), "=r"(r[3]) : "r"(addr));
}
__device__ __forceinline__ void ldsm2t(unsigned addr, unsigned* r) {
  asm volatile("ldmatrix.sync.aligned.m8n8.x2.trans.shared.b16 {%0,%1}, [%2];\n"
               : "=r"(r[0]), "=r"(r[1]) : "r"(addr));
}
__device__ __forceinline__ void mma_bf16(float* d, const unsigned* a,
                                         unsigned b0, unsigned b1) {
  asm volatile(
      "mma.sync.aligned.m16n8k16.row.col.f32.bf16.bf16.f32 "
      "{%0,%1,%2,%3}, {%4,%5,%6,%7}, {%8,%9}, {%0,%1,%2,%3};\n"
      : "+f"(d[0]), "+f"(d[1]), "+f"(d[2]), "+f"(d[3])
      : "r"(a[0]), "r"(a[1]), "r"(a[2]), "r"(a[3]), "r"(b0), "r"(b1));
}
__device__ __forceinline__ int aphys(int c, int r) {
  return (c < 24) ? ((c & ~7) | ((c & 7) ^ (r & 7))) : c;
}

__global__ __launch_bounds__(224, 3) void kC(int level, int Lin, int Lout, int npairs) {
  extern __shared__ char smc[];

  const __nv_bfloat16* src; __nv_bfloat16* dst;
  switch (level) {
    case 0:  src = g_P;  dst = g_b1; break;
    case 1:  src = g_b1; dst = g_b2; break;
    case 2:  src = g_b2; dst = g_b1; break;
    case 3:  src = g_b1; dst = g_b2; break;
    case 4:  src = g_b2; dst = g_b1; break;
    default: src = g_b1; dst = 0;    break;
  }

  const int xt  = blockIdx.x;            // 0..7: mt = xt&1, ct = xt>>1
  const int p   = blockIdx.y;
  const int b   = blockIdx.z;
  const int tid = threadIdx.x;

  if (p >= npairs) {                     // carry (levels with odd count only)
    const float4* Sg = (const float4*)(src + ((size_t)b*Lin + (Lin - 1))*MP2_);
    float4*       Dg = (float4*)(dst + ((size_t)b*Lout + npairs)*MP2_);
    const int q = MP2_*2/16/8;           // 784 float4 per x-tile
    for (int i = xt*q + tid; i < (xt + 1)*q; i += 224) Dg[i] = Sg[i];
    return;
  }

  const int mt = xt & 1, ct = xt >> 1;
  const int row0 = mt * 112;
  const int col0 = ct * 56;

  const char* Am = (const char*)(src + ((size_t)b*Lin + 2*p + 1)*MP2_);
  const char* Bm = (const char*)(src + ((size_t)b*Lin + 2*p    )*MP2_);

  // ---- single fill: A 112x26 chunks, B 208x8 chunks ----
  {
    const int r  = tid >> 1;
    const int cb = tid & 1;
#pragma unroll
    for (int i = 0; i < 13; ++i) {
      const int c = cb + 2*i;
      cpa16(smc + r*AROWB + aphys(c, r)*16, Am + (size_t)(row0 + r)*448 + c*16);
    }
    for (int idx = tid; idx < 208*8; idx += 224) {
      const int rr = idx >> 3, c = idx & 7;
      cpa16(smc + ABYTES + rr*BROWB + (c ^ (rr & 7))*16,
            Bm + (size_t)rr*448 + col0*2 + c*16);
    }
    asm volatile("cp.async.commit_group;\n" ::: "memory");
    asm volatile("cp.async.wait_group 0;\n" ::: "memory");
  }
  __syncthreads();

  const int lane = tid & 31;
  const int w    = tid >> 5;
  const int tg1  = (lane >> 3) & 1;
  const int tg2  = (lane >> 4) & 1;
  const int g    = lane >> 2;
  const int tig  = lane & 3;

  const int arow = w*16 + (lane & 7) + tg1*8;
  const unsigned aRowAddr = smem_u32p(smc) + arow*AROWB;
  const unsigned bBase    = smem_u32p(smc + ABYTES);
  const int bkoff = (lane & 7) + tg1*8;
  const int bk2off = ((lane & 15) & 7) + (((lane & 15) >> 3) & 1)*8;

  float acc[7][4];
#pragma unroll
  for (int nt = 0; nt < 7; ++nt)
#pragma unroll
    for (int j = 0; j < 4; ++j) acc[nt][j] = 0.f;

#pragma unroll
  for (int kk = 0; kk < KS_; ++kk) {
    unsigned aH[4];
    {
      const int ca = kk*2 + tg2;
      ldsm4(aRowAddr + aphys(ca, arow)*16, aH);
    }
    const int brow = kk*16 + bkoff;
    const int ksw  = brow & 7;
    const unsigned bRow = bBase + brow*BROWB;
#pragma unroll
    for (int jp = 0; jp < 3; ++jp) {
      const int cH = 2*jp + tg2;
      unsigned bb[4];
      ldsm4t(bRow + ((cH ^ ksw) << 4), bb);
      mma_bf16(acc[2*jp    ], aH, bb[0], bb[1]);
      mma_bf16(acc[2*jp + 1], aH, bb[2], bb[3]);
    }
    {
      const int r2  = kk*16 + bk2off;
      unsigned b2[2];
      ldsm2t(bBase + r2*BROWB + ((6 ^ (r2 & 7)) << 4), b2);
      mma_bf16(acc[6], aH, b2[0], b2[1]);
    }
  }

  // ---- epilogue ----
  const int r0g = row0 + w*16 + g;
  if (level < 5) {
    __nv_bfloat16* Cm = dst + ((size_t)b*Lout + p)*MP2_;
#pragma unroll
    for (int nt = 0; nt < 7; ++nt) {
      const int col = col0 + nt*8 + 2*tig;
      *(__nv_bfloat162*)(Cm + (size_t)r0g*NP_ + col) =
          __nv_bfloat162(__float2bfloat16_rn(acc[nt][0]), __float2bfloat16_rn(acc[nt][1]));
      *(__nv_bfloat162*)(Cm + (size_t)(r0g + 8)*NP_ + col) =
          __nv_bfloat162(__float2bfloat16_rn(acc[nt][2]), __float2bfloat16_rn(acc[nt][3]));
    }
  } else {
    float* Cm = g_At + (size_t)b*MP2_;
#pragma unroll
    for (int nt = 0; nt < 7; ++nt) {
      const int col = col0 + nt*8 + 2*tig;
      *(float2*)(Cm + (size_t)r0g*NP_ + col)       = make_float2(acc[nt][0], acc[nt][1]);
      *(float2*)(Cm + (size_t)(r0g + 8)*NP_ + col) = make_float2(acc[nt][2], acc[nt][3]);
    }
  }
}

// =============================================================================
// Kernel D: per-row loss/acc from final At (g_At, stride 224).
// =============================================================================
__global__ void kD() {
  __shared__ float sl[N_], sa[N_];
  const int b = blockIdx.x, n = threadIdx.x;
  const float* row = g_At + (size_t)b*MP2_ + (size_t)n*NP_;
  float rs = 0.f, best = -1.f;
  int bi = 0;
  for (int m = 0; m < N_; ++m) {
    const float v = row[m];
    rs += v;
    if (v > best) { best = v; bi = m; }
  }
  const float diag = row[n];
  sl[n] = logf(rs + (float)N_ * EPS_) - logf(diag + EPS_);
  sa[n] = (bi == n) ? 1.f : 0.f;
  __syncthreads();
  if (n == 0) {
    float L = 0.f, A = 0.f;
    for (int i = 0; i < N_; ++i) { L += sl[i]; A += sa[i]; }
    g_partial[b]      = L;
    g_partial[B_ + b] = A;
  }
}

__global__ void kE(float* out, int out_size) {
  float L = 0.f, A = 0.f;
  for (int b = 0; b < B_; ++b) { L += g_partial[b]; A += g_partial[B_ + b]; }
  const float inv = 1.0f / (float)(B_ * N_);
  if (out_size > QSIZE)     out[QSIZE]     = L * inv;
  if (out_size > QSIZE + 1) out[QSIZE + 1] = A * inv;
}

// =============================================================================
extern "C" void kernel_launch(void* const* d_in, const int* in_sizes, int n_in,
                              void* d_out, int out_size) {
  const float* maps = (const float*)d_in[0];
  const float* W    = (const float*)d_in[1];
  const float* bias = (const float*)d_in[2];
  float* out = (float*)d_out;

  cudaFuncSetAttribute(kA, cudaFuncAttributeMaxDynamicSharedMemorySize, (int)SMEM_A_BYTES);
  cudaFuncSetAttribute(kB, cudaFuncAttributeMaxDynamicSharedMemorySize, (int)SMEM_B_BYTES);
  cudaFuncSetAttribute(kC, cudaFuncAttributeMaxDynamicSharedMemorySize, (int)SMEM_C_BYTES);

  kA<<<B_*N_, 128, SMEM_A_BYTES>>>(maps, W, bias, out);
  kB<<<dim3(T_ - 1, B_), 392, SMEM_B_BYTES>>>();

  // product tree: 38 -> 19 -> 10 -> 5 -> 3 -> 2 -> 1
  // {level, Lin, Lout, npairs, carry}
  const int lv[6][5] = {
    {0, 38, 19, 19, 0},
    {1, 19, 10,  9, 1},
    {2, 10,  5,  5, 0},
    {3,  5,  3,  2, 1},
    {4,  3,  2,  1, 1},
    {5,  2,  1,  1, 0},
  };
  for (int l = 0; l < 6; ++l) {
    kC<<<dim3(8, lv[l][3] + lv[l][4], B_), 224, SMEM_C_BYTES>>>(
        lv[l][0], lv[l][1], lv[l][2], lv[l][3]);
  }

  kD<<<B_, N_>>>();
  kE<<<1, 1>>>(out, out_size);
}

// round 7
// speedup vs baseline: 3.2583x; 1.4489x over previous
#include <cuda_runtime.h>
#include <cuda_bf16.h>
#include <math.h>

#define B_ 16
#define N_ 196
#define C_ 512
#define T_ 20
#define D_ 128
#define S_ 38
#define NP_ 224                    // padded row/col stride for chain matrices
#define MP2_ (NP_*NP_)             // 50176 elems per padded matrix
#define M_ 62720                   // B*N*T rows of the head GEMM (=490*128)
#define QSIZE 8028160              // B*D*T*N
#define INV_TEMP (1.0f/0.07f)
#define EPS_ 1e-20f

// ---------------- scratch (static device globals; no allocation) ----------------
__device__ float g_qA[B_*T_*N_*D_];                                  // [b][t][n][d]
__device__ __align__(256) __nv_bfloat16 g_qpH[(size_t)M_*C_];        // pooled acts hi
__device__ __align__(256) __nv_bfloat16 g_qpL[(size_t)M_*C_];        // pooled acts lo
__device__ __align__(256) __nv_bfloat16 g_WH[C_*D_];                 // W hi
__device__ __align__(256) __nv_bfloat16 g_WL[C_*D_];                 // W lo
__device__ __align__(256) __nv_bfloat16 g_P [(size_t)B_*S_*MP2_ + 256];
__device__ __align__(256) __nv_bfloat16 g_b1[(size_t)B_*19*MP2_ + 256];
__device__ __align__(256) __nv_bfloat16 g_b2[(size_t)B_*10*MP2_ + 256];
__device__ float g_At[(size_t)B_*MP2_];                              // final product fp32
__device__ float g_partial[2*B_];

// ---------------- packed fp32x2 FMA helpers --------------------------------
__device__ __forceinline__ unsigned long long pk2(float x, float y) {
  unsigned long long r;
  asm("mov.b64 %0, {%1,%2};" : "=l"(r) : "f"(x), "f"(y));
  return r;
}
__device__ __forceinline__ void fma2(unsigned long long& d,
                                     unsigned long long a, unsigned long long b) {
  asm("fma.rn.f32x2 %0, %1, %2, %0;" : "+l"(d) : "l"(a), "l"(b));
}
__device__ __forceinline__ float2 upk2(unsigned long long v) {
  float2 f;
  asm("mov.b64 {%0,%1}, %2;" : "=f"(f.x), "=f"(f.y) : "l"(v));
  return f;
}

// ---------------- mma / ldmatrix / cp.async helpers -------------------------
__device__ __forceinline__ void cpa16(void* dst_smem, const void* src) {
  unsigned d = (unsigned)__cvta_generic_to_shared(dst_smem);
  asm volatile("cp.async.cg.shared.global [%0], [%1], 16;\n" :: "r"(d), "l"(src));
}
__device__ __forceinline__ unsigned smem_u32p(const void* p) {
  return (unsigned)__cvta_generic_to_shared(p);
}
__device__ __forceinline__ void ldsm4(unsigned addr, unsigned* r) {
  asm volatile("ldmatrix.sync.aligned.m8n8.x4.shared.b16 {%0,%1,%2,%3}, [%4];\n"
               : "=r"(r[0]), "=r"(r[1]), "=r"(r[2]), "=r"(r[3]) : "r"(addr));
}
__device__ __forceinline__ void ldsm4t(unsigned addr, unsigned* r) {
  asm volatile("ldmatrix.sync.aligned.m8n8.x4.trans.shared.b16 {%0,%1,%2,%3}, [%4];\n"
               : "=r"(r[0]), "=r"(r[1]), "=r"(r[2]), "=r"(r[3]) : "r"(addr));
}
__device__ __forceinline__ void ldsm2t(unsigned addr, unsigned* r) {
  asm volatile("ldmatrix.sync.aligned.m8n8.x2.trans.shared.b16 {%0,%1}, [%2];\n"
               : "=r"(r[0]), "=r"(r[1]) : "r"(addr));
}
__device__ __forceinline__ void mma_bf16(float* d, const unsigned* a,
                                         unsigned b0, unsigned b1) {
  asm volatile(
      "mma.sync.aligned.m16n8k16.row.col.f32.bf16.bf16.f32 "
      "{%0,%1,%2,%3}, {%4,%5,%6,%7}, {%8,%9}, {%0,%1,%2,%3};\n"
      : "+f"(d[0]), "+f"(d[1]), "+f"(d[2]), "+f"(d[3])
      : "r"(a[0]), "r"(a[1]), "r"(a[2]), "r"(a[3]), "r"(b0), "r"(b1));
}

// =============================================================================
// Kernel P: spatial pool + bf16 hi/lo split of pooled activations.
// CTA per bn; reads maps (coalesced float4 stream), writes A[m=bn*20+t][c]
// as two bf16 planes (k-contiguous rows -> coalesced).
// =============================================================================
#define SMEM_P_BYTES (C_*21*sizeof(float))

__global__ __launch_bounds__(128) void kP(const float* __restrict__ maps) {
  extern __shared__ float qp[];             // [c][t] stride 21
  const int bn = blockIdx.x, tid = threadIdx.x;
  const float4* src = reinterpret_cast<const float4*>(maps) + (size_t)bn * (C_*T_);
  for (int i = tid; i < C_*T_; i += 128) {
    float4 v = src[i];
    const int c = i / 20, t = i - c*20;
    qp[c*21 + t] = (v.x + v.y + v.z + v.w) * 0.25f;
  }
  __syncthreads();
  __nv_bfloat16* AH = g_qpH + (size_t)bn*20*C_;
  __nv_bfloat16* AL = g_qpL + (size_t)bn*20*C_;
  for (int i = tid; i < 20*C_; i += 128) {
    const int t = i >> 9, c = i & 511;
    const float x = qp[c*21 + t];
    const __nv_bfloat16 h = __float2bfloat16_rn(x);
    AH[t*C_ + c] = h;
    AL[t*C_ + c] = __float2bfloat16_rn(x - __bfloat162float(h));
  }
}

// W split (512x128 -> H/L planes)
__global__ void kW(const float* __restrict__ W) {
  const int i = blockIdx.x*256 + threadIdx.x;   // grid 256 x 256 = 65536
  const float x = W[i];
  const __nv_bfloat16 h = __float2bfloat16_rn(x);
  g_WH[i] = h;
  g_WL[i] = __float2bfloat16_rn(x - __bfloat162float(h));
}

// =============================================================================
// Kernel G: head GEMM on tensor cores. y[M,128] = A[M,512] @ W[512,128], bf16
// 3-pass split (AH*WH + AH*WL + AL*WH), fp32 accum. CTA 128m x 128n, 256 thr
// (8 warps = 4m x 2n, warp 32m x 64n). K chunk 32, cp.async double buffered.
// A smem rows stride 80B (5 chunks -> conflict-free, no xor); B xor-swizzled.
// Fused epilogue: +bias, L2-normalize rows, write g_qA.
// =============================================================================
#define GSTAGE 36864
#define SMEM_G_BYTES (2*GSTAGE)             // 73728

__global__ __launch_bounds__(256, 2) void kG(const float* __restrict__ bias) {
  extern __shared__ char smg[];
  const int m0  = blockIdx.x * 128;
  const int tid = threadIdx.x;
  const int lane = tid & 31, w = tid >> 5;
  const int wm = w & 3, nh = w >> 2;
  const int g = lane >> 2, tig = lane & 3;
  const int tg1 = (lane >> 3) & 1, tg2 = (lane >> 4) & 1;

  const __nv_bfloat16* AmH = g_qpH + (size_t)m0*C_;
  const __nv_bfloat16* AmL = g_qpL + (size_t)m0*C_;

  float acc[2][8][4];
#pragma unroll
  for (int mt = 0; mt < 2; ++mt)
#pragma unroll
    for (int nt = 0; nt < 8; ++nt)
#pragma unroll
      for (int j = 0; j < 4; ++j) acc[mt][nt][j] = 0.f;

  auto fill = [&](int stg, int k0) {
    char* S = smg + stg*GSTAGE;
#pragma unroll
    for (int i = 0; i < 4; ++i) {          // A: 128 rows x 4 chunks x 2 planes
      const int idx = tid + i*256;
      const int r = idx >> 3, z = idx & 7;
      const int pl = z >> 2, c = z & 3;
      cpa16(S + pl*10240 + r*80 + c*16,
            (pl ? AmL : AmH) + (size_t)r*C_ + k0 + c*8);
    }
#pragma unroll
    for (int i = 0; i < 4; ++i) {          // B: 32 rows x 16 chunks x 2 planes
      const int idx = tid + i*256;
      const int r = idx >> 5, z = idx & 31;
      const int pl = z >> 4, c = z & 15;
      const int ph = (c & 8) | ((c & 7) ^ (r & 7));
      cpa16(S + 20480 + pl*8192 + r*256 + ph*16,
            (pl ? g_WL : g_WH) + (size_t)(k0 + r)*D_ + c*8);
    }
    asm volatile("cp.async.commit_group;\n" ::: "memory");
  };

  fill(0, 0);
  for (int s = 0; s < 16; ++s) {
    if (s + 1 < 16) {
      fill((s + 1) & 1, (s + 1)*32);
      asm volatile("cp.async.wait_group 1;\n" ::: "memory");
    } else {
      asm volatile("cp.async.wait_group 0;\n" ::: "memory");
    }
    __syncthreads();

    const char* S = smg + (s & 1)*GSTAGE;
    const unsigned sBase = smem_u32p(S);
    const int arow = wm*32 + (lane & 7) + tg1*8;

#pragma unroll
    for (int ks = 0; ks < 2; ++ks) {
      unsigned aH[2][4], aL[2][4];
#pragma unroll
      for (int mt = 0; mt < 2; ++mt) {
        const unsigned ar = sBase + (arow + mt*16)*80 + (ks*2 + tg2)*16;
        ldsm4(ar, aH[mt]);
        ldsm4(ar + 10240, aL[mt]);
      }
      const int brow = ks*16 + (lane & 7) + tg1*8;
#pragma unroll
      for (int jp = 0; jp < 4; ++jp) {
        const int c  = nh*8 + 2*jp + tg2;
        const int ph = (c & 8) | ((c & 7) ^ (brow & 7));
        const unsigned ba = sBase + 20480 + brow*256 + ph*16;
        unsigned bH[4], bL[4];
        ldsm4t(ba, bH);
        ldsm4t(ba + 8192, bL);
#pragma unroll
        for (int mt = 0; mt < 2; ++mt) {
          mma_bf16(acc[mt][2*jp    ], aH[mt], bH[0], bH[1]);
          mma_bf16(acc[mt][2*jp    ], aH[mt], bL[0], bL[1]);
          mma_bf16(acc[mt][2*jp    ], aL[mt], bH[0], bH[1]);
          mma_bf16(acc[mt][2*jp + 1], aH[mt], bH[2], bH[3]);
          mma_bf16(acc[mt][2*jp + 1], aH[mt], bL[2], bL[3]);
          mma_bf16(acc[mt][2*jp + 1], aL[mt], bH[2], bH[3]);
        }
      }
    }
    __syncthreads();
  }

  // ---- fused epilogue: stage y to smem, +bias, row L2 norm, write g_qA ----
  float* y       = (float*)smg;            // [128][129]
  float* partial = y + 128*129;            // [128][2]
  float* inorm   = partial + 256;          // [128]
#pragma unroll
  for (int mt = 0; mt < 2; ++mt) {
    const int row = wm*32 + mt*16 + g;
#pragma unroll
    for (int nt = 0; nt < 8; ++nt) {
      const int col = nh*64 + nt*8 + 2*tig;
      y[ row     *129 + col    ] = acc[mt][nt][0];
      y[ row     *129 + col + 1] = acc[mt][nt][1];
      y[(row + 8)*129 + col    ] = acc[mt][nt][2];
      y[(row + 8)*129 + col + 1] = acc[mt][nt][3];
    }
  }
  __syncthreads();
  {
    const int r = tid >> 1, hf = tid & 1;
    float ssum = 0.f;
#pragma unroll 8
    for (int d = hf*64; d < hf*64 + 64; ++d) {
      const float v = y[r*129 + d] + bias[d];
      y[r*129 + d] = v;
      ssum += v*v;
    }
    partial[r*2 + hf] = ssum;
  }
  __syncthreads();
  if (tid < 128)
    inorm[tid] = 1.0f / fmaxf(sqrtf(partial[tid*2] + partial[tid*2 + 1]), 1e-12f);
  __syncthreads();
  for (int i = tid; i < 128*128; i += 256) {
    const int rr = i >> 7, d = i & 127;
    const int m  = m0 + rr;
    const int bn = m / 20, t = m - bn*20;
    const int bq = bn / N_, n = bn - bq*N_;
    g_qA[((size_t)(bq*T_ + t)*N_ + n)*D_ + d] = y[rr*129 + d] * inorm[rr];
  }
}

// =============================================================================
// Kernel Q: transpose q to output layout (B, d, T, N). CTA per (t, b).
// Read g_qA coalesced in d; write qout coalesced in n via padded smem tile.
// =============================================================================
#define SMEM_Q_BYTES (N_*129*sizeof(float))

__global__ __launch_bounds__(256) void kQ(float* __restrict__ qout) {
  extern __shared__ float sq[];            // [n][d] stride 129
  const int t = blockIdx.x, b = blockIdx.y, tid = threadIdx.x;
  const float* src = g_qA + ((size_t)(b*T_ + t)*N_)*D_;
  for (int i = tid; i < N_*D_; i += 256) {
    const int n = i >> 7, d = i & 127;
    sq[n*129 + d] = src[i];
  }
  __syncthreads();
  for (int i = tid; i < N_*D_; i += 256) {
    const int d = i / N_, n = i - d*N_;
    qout[((size_t)(b*D_ + d)*T_ + t)*N_ + n] = sq[n*129 + d];
  }
}

// =============================================================================
// Kernel B: affinity + palindrome softmax -> bf16 P planes. (unchanged R6)
// =============================================================================
#define SMEM_B_BYTES ((N_*197 + 2*16*N_) * sizeof(float))

__global__ __launch_bounds__(392) void kB() {
  extern __shared__ float sm[];
  float* Sm = sm;                    // 196 x 197
  float* Qa = sm + N_*197;           // 16 x 196
  float* Qb = Qa + 16*N_;            // 16 x 196

  const int t   = blockIdx.x;
  const int b   = blockIdx.y;
  const int tid = threadIdx.x;
  const int ty  = tid / 14, tx = tid % 14;
  const int r0  = ty * 7,   c0 = tx * 14;

  const float* qa_base = g_qA + (size_t)((b*T_ + t    )*N_) * D_;
  const float* qb_base = g_qA + (size_t)((b*T_ + t + 1)*N_) * D_;

  unsigned long long acc2[7][7];
#pragma unroll
  for (int i = 0; i < 7; ++i)
#pragma unroll
    for (int j = 0; j < 7; ++j) acc2[i][j] = 0ULL;

  for (int k0 = 0; k0 < D_; k0 += 16) {
    __syncthreads();
    for (int idx = tid; idx < N_*16; idx += 392) {
      const int n = idx >> 4, k = idx & 15;
      Qa[k*N_ + n] = qa_base[(size_t)n*D_ + k0 + k];
      Qb[k*N_ + n] = qb_base[(size_t)n*D_ + k0 + k];
    }
    __syncthreads();
#pragma unroll
    for (int k = 0; k < 16; ++k) {
      unsigned long long ra2[7], rb2[7];
#pragma unroll
      for (int i = 0; i < 7; ++i) {
        const float a = Qa[k*N_ + r0 + i];
        ra2[i] = pk2(a, a);
      }
#pragma unroll
      for (int j = 0; j < 7; ++j)
        rb2[j] = pk2(Qb[k*N_ + c0 + 2*j], Qb[k*N_ + c0 + 2*j + 1]);
#pragma unroll
      for (int i = 0; i < 7; ++i)
#pragma unroll
        for (int j = 0; j < 7; ++j) fma2(acc2[i][j], ra2[i], rb2[j]);
    }
  }
  __syncthreads();

#pragma unroll
  for (int i = 0; i < 7; ++i)
#pragma unroll
    for (int j = 0; j < 7; ++j) {
      float2 v = upk2(acc2[i][j]);
      Sm[(r0 + i)*197 + (c0 + 2*j)    ] = v.x * INV_TEMP;
      Sm[(r0 + i)*197 + (c0 + 2*j + 1)] = v.y * INV_TEMP;
    }
  __syncthreads();

  for (int idx = tid; idx < N_*N_; idx += 392) {
    const int rr = idx / N_, mm = idx - rr*N_;
    Sm[rr*197 + mm] = __expf(Sm[rr*197 + mm]);
  }
  __syncthreads();

  float* rinv = Qa;
  float* cinv = Qa + N_;
  if (tid < N_) {
    float rs = 0.f, cs = 0.f;
    for (int m = 0; m < N_; ++m) {
      rs += Sm[tid*197 + m];
      cs += Sm[m*197 + tid];
    }
    rinv[tid] = 1.0f / rs;
    cinv[tid] = 1.0f / cs;
  }
  __syncthreads();

  __nv_bfloat16* Pf = g_P + (size_t)(b*S_ + t       )*MP2_;
  __nv_bfloat16* Pb = g_P + (size_t)(b*S_ + (37 - t))*MP2_;
  for (int idx = tid; idx < MP2_/2; idx += 392) {
    const int rr = idx / 112;
    const int m2 = (idx - rr*112) * 2;
    float vf0 = 0.f, vf1 = 0.f, vb0 = 0.f, vb1 = 0.f;
    if (rr < N_ && m2 < N_) {
      vf0 = Sm[rr*197 + m2] * rinv[rr];
      vb0 = Sm[m2*197 + rr] * cinv[rr];
      if (m2 + 1 < N_) {
        vf1 = Sm[rr*197 + m2 + 1] * rinv[rr];
        vb1 = Sm[(m2 + 1)*197 + rr] * cinv[rr];
      }
    }
    *(__nv_bfloat162*)(Pf + (size_t)rr*NP_ + m2) =
        __nv_bfloat162(__float2bfloat16_rn(vf0), __float2bfloat16_rn(vf1));
    *(__nv_bfloat162*)(Pb + (size_t)rr*NP_ + m2) =
        __nv_bfloat162(__float2bfloat16_rn(vb0), __float2bfloat16_rn(vb1));
  }
}

// =============================================================================
// Kernel C: product-tree GEMM, pure bf16 whole-tile smem. (unchanged R6)
// =============================================================================
#define KS_ 13
#define AROWB 416
#define ABYTES (112*AROWB)
#define BROWB 128
#define BBYTES (208*BROWB)
#define SMEM_C_BYTES (ABYTES + BBYTES)

__device__ __forceinline__ int aphys(int c, int r) {
  return (c < 24) ? ((c & ~7) | ((c & 7) ^ (r & 7))) : c;
}

__global__ __launch_bounds__(224, 3) void kC(int level, int Lin, int Lout, int npairs) {
  extern __shared__ char smc[];

  const __nv_bfloat16* src; __nv_bfloat16* dst;
  switch (level) {
    case 0:  src = g_P;  dst = g_b1; break;
    case 1:  src = g_b1; dst = g_b2; break;
    case 2:  src = g_b2; dst = g_b1; break;
    case 3:  src = g_b1; dst = g_b2; break;
    case 4:  src = g_b2; dst = g_b1; break;
    default: src = g_b1; dst = 0;    break;
  }

  const int xt  = blockIdx.x;
  const int p   = blockIdx.y;
  const int b   = blockIdx.z;
  const int tid = threadIdx.x;

  if (p >= npairs) {
    const float4* Sg = (const float4*)(src + ((size_t)b*Lin + (Lin - 1))*MP2_);
    float4*       Dg = (float4*)(dst + ((size_t)b*Lout + npairs)*MP2_);
    const int q = MP2_*2/16/8;
    for (int i = xt*q + tid; i < (xt + 1)*q; i += 224) Dg[i] = Sg[i];
    return;
  }

  const int mt = xt & 1, ct = xt >> 1;
  const int row0 = mt * 112;
  const int col0 = ct * 56;

  const char* Am = (const char*)(src + ((size_t)b*Lin + 2*p + 1)*MP2_);
  const char* Bm = (const char*)(src + ((size_t)b*Lin + 2*p    )*MP2_);

  {
    const int r  = tid >> 1;
    const int cb = tid & 1;
#pragma unroll
    for (int i = 0; i < 13; ++i) {
      const int c = cb + 2*i;
      cpa16(smc + r*AROWB + aphys(c, r)*16, Am + (size_t)(row0 + r)*448 + c*16);
    }
    for (int idx = tid; idx < 208*8; idx += 224) {
      const int rr = idx >> 3, c = idx & 7;
      cpa16(smc + ABYTES + rr*BROWB + (c ^ (rr & 7))*16,
            Bm + (size_t)rr*448 + col0*2 + c*16);
    }
    asm volatile("cp.async.commit_group;\n" ::: "memory");
    asm volatile("cp.async.wait_group 0;\n" ::: "memory");
  }
  __syncthreads();

  const int lane = tid & 31;
  const int w    = tid >> 5;
  const int tg1  = (lane >> 3) & 1;
  const int tg2  = (lane >> 4) & 1;
  const int g    = lane >> 2;
  const int tig  = lane & 3;

  const int arow = w*16 + (lane & 7) + tg1*8;
  const unsigned aRowAddr = smem_u32p(smc) + arow*AROWB;
  const unsigned bBase    = smem_u32p(smc + ABYTES);
  const int bkoff = (lane & 7) + tg1*8;
  const int bk2off = ((lane & 15) & 7) + (((lane & 15) >> 3) & 1)*8;

  float acc[7][4];
#pragma unroll
  for (int nt = 0; nt < 7; ++nt)
#pragma unroll
    for (int j = 0; j < 4; ++j) acc[nt][j] = 0.f;

#pragma unroll
  for (int kk = 0; kk < KS_; ++kk) {
    unsigned aH[4];
    {
      const int ca = kk*2 + tg2;
      ldsm4(aRowAddr + aphys(ca, arow)*16, aH);
    }
    const int brow = kk*16 + bkoff;
    const int ksw  = brow & 7;
    const unsigned bRow = bBase + brow*BROWB;
#pragma unroll
    for (int jp = 0; jp < 3; ++jp) {
      const int cH = 2*jp + tg2;
      unsigned bb[4];
      ldsm4t(bRow + ((cH ^ ksw) << 4), bb);
      mma_bf16(acc[2*jp    ], aH, bb[0], bb[1]);
      mma_bf16(acc[2*jp + 1], aH, bb[2], bb[3]);
    }
    {
      const int r2  = kk*16 + bk2off;
      unsigned b2[2];
      ldsm2t(bBase + r2*BROWB + ((6 ^ (r2 & 7)) << 4), b2);
      mma_bf16(acc[6], aH, b2[0], b2[1]);
    }
  }

  const int r0g = row0 + w*16 + g;
  if (level < 5) {
    __nv_bfloat16* Cm = dst + ((size_t)b*Lout + p)*MP2_;
#pragma unroll
    for (int nt = 0; nt < 7; ++nt) {
      const int col = col0 + nt*8 + 2*tig;
      *(__nv_bfloat162*)(Cm + (size_t)r0g*NP_ + col) =
          __nv_bfloat162(__float2bfloat16_rn(acc[nt][0]), __float2bfloat16_rn(acc[nt][1]));
      *(__nv_bfloat162*)(Cm + (size_t)(r0g + 8)*NP_ + col) =
          __nv_bfloat162(__float2bfloat16_rn(acc[nt][2]), __float2bfloat16_rn(acc[nt][3]));
    }
  } else {
    float* Cm = g_At + (size_t)b*MP2_;
#pragma unroll
    for (int nt = 0; nt < 7; ++nt) {
      const int col = col0 + nt*8 + 2*tig;
      *(float2*)(Cm + (size_t)r0g*NP_ + col)       = make_float2(acc[nt][0], acc[nt][1]);
      *(float2*)(Cm + (size_t)(r0g + 8)*NP_ + col) = make_float2(acc[nt][2], acc[nt][3]);
    }
  }
}

// =============================================================================
// Kernel D/E: loss + acc. (unchanged)
// =============================================================================
__global__ void kD() {
  __shared__ float sl[N_], sa[N_];
  const int b = blockIdx.x, n = threadIdx.x;
  const float* row = g_At + (size_t)b*MP2_ + (size_t)n*NP_;
  float rs = 0.f, best = -1.f;
  int bi = 0;
  for (int m = 0; m < N_; ++m) {
    const float v = row[m];
    rs += v;
    if (v > best) { best = v; bi = m; }
  }
  const float diag = row[n];
  sl[n] = logf(rs + (float)N_ * EPS_) - logf(diag + EPS_);
  sa[n] = (bi == n) ? 1.f : 0.f;
  __syncthreads();
  if (n == 0) {
    float L = 0.f, A = 0.f;
    for (int i = 0; i < N_; ++i) { L += sl[i]; A += sa[i]; }
    g_partial[b]      = L;
    g_partial[B_ + b] = A;
  }
}

__global__ void kE(float* out, int out_size) {
  float L = 0.f, A = 0.f;
  for (int b = 0; b < B_; ++b) { L += g_partial[b]; A += g_partial[B_ + b]; }
  const float inv = 1.0f / (float)(B_ * N_);
  if (out_size > QSIZE)     out[QSIZE]     = L * inv;
  if (out_size > QSIZE + 1) out[QSIZE + 1] = A * inv;
}

// =============================================================================
extern "C" void kernel_launch(void* const* d_in, const int* in_sizes, int n_in,
                              void* d_out, int out_size) {
  const float* maps = (const float*)d_in[0];
  const float* W    = (const float*)d_in[1];
  const float* bias = (const float*)d_in[2];
  float* out = (float*)d_out;

  cudaFuncSetAttribute(kP, cudaFuncAttributeMaxDynamicSharedMemorySize, (int)SMEM_P_BYTES);
  cudaFuncSetAttribute(kG, cudaFuncAttributeMaxDynamicSharedMemorySize, (int)SMEM_G_BYTES);
  cudaFuncSetAttribute(kQ, cudaFuncAttributeMaxDynamicSharedMemorySize, (int)SMEM_Q_BYTES);
  cudaFuncSetAttribute(kB, cudaFuncAttributeMaxDynamicSharedMemorySize, (int)SMEM_B_BYTES);
  cudaFuncSetAttribute(kC, cudaFuncAttributeMaxDynamicSharedMemorySize, (int)SMEM_C_BYTES);

  kP<<<B_*N_, 128, SMEM_P_BYTES>>>(maps);
  kW<<<256, 256>>>(W);
  kG<<<M_/128, 256, SMEM_G_BYTES>>>(bias);
  kB<<<dim3(T_ - 1, B_), 392, SMEM_B_BYTES>>>();
  kQ<<<dim3(T_, B_), 256, SMEM_Q_BYTES>>>(out);

  // product tree: 38 -> 19 -> 10 -> 5 -> 3 -> 2 -> 1
  const int lv[6][5] = {
    {0, 38, 19, 19, 0},
    {1, 19, 10,  9, 1},
    {2, 10,  5,  5, 0},
    {3,  5,  3,  2, 1},
    {4,  3,  2,  1, 1},
    {5,  2,  1,  1, 0},
  };
  for (int l = 0; l < 6; ++l) {
    kC<<<dim3(8, lv[l][3] + lv[l][4], B_), 224, SMEM_C_BYTES>>>(
        lv[l][0], lv[l][1], lv[l][2], lv[l][3]);
  }

  kD<<<B_, N_>>>();
  kE<<<1, 1>>>(out, out_size);
}

// round 8
// speedup vs baseline: 3.8682x; 1.1872x over previous
#include <cuda_runtime.h>
#include <cuda_bf16.h>
#include <math.h>

#define B_ 16
#define N_ 196
#define C_ 512
#define T_ 20
#define D_ 128
#define S_ 38
#define NP_ 224                    // padded row/col stride for chain matrices
#define MP2_ (NP_*NP_)             // 50176 elems per padded matrix
#define M_ 62720                   // B*N*T rows of the head GEMM (=490*128)
#define QSIZE 8028160              // B*D*T*N
#define INV_TEMP (1.0f/0.07f)
#define EPS_ 1e-20f

// ---------------- scratch (static device globals; no allocation) ----------------
__device__ float g_qA[B_*T_*N_*D_];                                  // [b][t][n][d] fp32
__device__ __align__(256) __nv_bfloat16 g_qbf[B_*T_*N_*D_];          // bf16 copy of q
__device__ __align__(256) __nv_bfloat16 g_qpH[(size_t)M_*C_];        // pooled acts hi
__device__ __align__(256) __nv_bfloat16 g_qpL[(size_t)M_*C_];        // pooled acts lo
__device__ __align__(256) __nv_bfloat16 g_WH[C_*D_];                 // W hi
__device__ __align__(256) __nv_bfloat16 g_WL[C_*D_];                 // W lo
__device__ __align__(256) __nv_bfloat16 g_P [(size_t)B_*S_*MP2_ + 256];
__device__ __align__(256) __nv_bfloat16 g_b1[(size_t)B_*19*MP2_ + 256];
__device__ __align__(256) __nv_bfloat16 g_b2[(size_t)B_*10*MP2_ + 256];
__device__ float g_At[(size_t)B_*MP2_];                              // final product fp32
__device__ float g_partial[2*B_];

// ---------------- mma / ldmatrix / cp.async helpers -------------------------
__device__ __forceinline__ void cpa16(void* dst_smem, const void* src) {
  unsigned d = (unsigned)__cvta_generic_to_shared(dst_smem);
  asm volatile("cp.async.cg.shared.global [%0], [%1], 16;\n" :: "r"(d), "l"(src));
}
__device__ __forceinline__ unsigned smem_u32p(const void* p) {
  return (unsigned)__cvta_generic_to_shared(p);
}
__device__ __forceinline__ void ldsm4(unsigned addr, unsigned* r) {
  asm volatile("ldmatrix.sync.aligned.m8n8.x4.shared.b16 {%0,%1,%2,%3}, [%4];\n"
               : "=r"(r[0]), "=r"(r[1]), "=r"(r[2]), "=r"(r[3]) : "r"(addr));
}
__device__ __forceinline__ void ldsm4t(unsigned addr, unsigned* r) {
  asm volatile("ldmatrix.sync.aligned.m8n8.x4.trans.shared.b16 {%0,%1,%2,%3}, [%4];\n"
               : "=r"(r[0]), "=r"(r[1]), "=r"(r[2]), "=r"(r[3]) : "r"(addr));
}
__device__ __forceinline__ void ldsm2t(unsigned addr, unsigned* r) {
  asm volatile("ldmatrix.sync.aligned.m8n8.x2.trans.shared.b16 {%0,%1}, [%2];\n"
               : "=r"(r[0]), "=r"(r[1]) : "r"(addr));
}
__device__ __forceinline__ void mma_bf16(float* d, const unsigned* a,
                                         unsigned b0, unsigned b1) {
  asm volatile(
      "mma.sync.aligned.m16n8k16.row.col.f32.bf16.bf16.f32 "
      "{%0,%1,%2,%3}, {%4,%5,%6,%7}, {%8,%9}, {%0,%1,%2,%3};\n"
      : "+f"(d[0]), "+f"(d[1]), "+f"(d[2]), "+f"(d[3])
      : "r"(a[0]), "r"(a[1]), "r"(a[2]), "r"(a[3]), "r"(b0), "r"(b1));
}

// =============================================================================
// Kernel P: spatial pool + bf16 hi/lo split of pooled activations. (unchanged)
// =============================================================================
#define SMEM_P_BYTES (C_*21*sizeof(float))

__global__ __launch_bounds__(128) void kP(const float* __restrict__ maps) {
  extern __shared__ float qp[];             // [c][t] stride 21
  const int bn = blockIdx.x, tid = threadIdx.x;
  const float4* src = reinterpret_cast<const float4*>(maps) + (size_t)bn * (C_*T_);
  for (int i = tid; i < C_*T_; i += 128) {
    float4 v = src[i];
    const int c = i / 20, t = i - c*20;
    qp[c*21 + t] = (v.x + v.y + v.z + v.w) * 0.25f;
  }
  __syncthreads();
  __nv_bfloat16* AH = g_qpH + (size_t)bn*20*C_;
  __nv_bfloat16* AL = g_qpL + (size_t)bn*20*C_;
  for (int i = tid; i < 20*C_; i += 128) {
    const int t = i >> 9, c = i & 511;
    const float x = qp[c*21 + t];
    const __nv_bfloat16 h = __float2bfloat16_rn(x);
    AH[t*C_ + c] = h;
    AL[t*C_ + c] = __float2bfloat16_rn(x - __bfloat162float(h));
  }
}

// W split (512x128 -> H/L planes)
__global__ void kW(const float* __restrict__ W) {
  const int i = blockIdx.x*256 + threadIdx.x;   // grid 256 x 256 = 65536
  const float x = W[i];
  const __nv_bfloat16 h = __float2bfloat16_rn(x);
  g_WH[i] = h;
  g_WL[i] = __float2bfloat16_rn(x - __bfloat162float(h));
}

// =============================================================================
// Kernel G: head GEMM on tensor cores (3-pass bf16 split, fused bias+norm).
// Also emits bf16 q plane for kB. (otherwise unchanged from R7)
// =============================================================================
#define GSTAGE 36864
#define SMEM_G_BYTES (2*GSTAGE)             // 73728

__global__ __launch_bounds__(256, 2) void kG(const float* __restrict__ bias) {
  extern __shared__ char smg[];
  const int m0  = blockIdx.x * 128;
  const int tid = threadIdx.x;
  const int lane = tid & 31, w = tid >> 5;
  const int wm = w & 3, nh = w >> 2;
  const int g = lane >> 2, tig = lane & 3;
  const int tg1 = (lane >> 3) & 1, tg2 = (lane >> 4) & 1;

  const __nv_bfloat16* AmH = g_qpH + (size_t)m0*C_;
  const __nv_bfloat16* AmL = g_qpL + (size_t)m0*C_;

  float acc[2][8][4];
#pragma unroll
  for (int mt = 0; mt < 2; ++mt)
#pragma unroll
    for (int nt = 0; nt < 8; ++nt)
#pragma unroll
      for (int j = 0; j < 4; ++j) acc[mt][nt][j] = 0.f;

  auto fill = [&](int stg, int k0) {
    char* S = smg + stg*GSTAGE;
#pragma unroll
    for (int i = 0; i < 4; ++i) {
      const int idx = tid + i*256;
      const int r = idx >> 3, z = idx & 7;
      const int pl = z >> 2, c = z & 3;
      cpa16(S + pl*10240 + r*80 + c*16,
            (pl ? AmL : AmH) + (size_t)r*C_ + k0 + c*8);
    }
#pragma unroll
    for (int i = 0; i < 4; ++i) {
      const int idx = tid + i*256;
      const int r = idx >> 5, z = idx & 31;
      const int pl = z >> 4, c = z & 15;
      const int ph = (c & 8) | ((c & 7) ^ (r & 7));
      cpa16(S + 20480 + pl*8192 + r*256 + ph*16,
            (pl ? g_WL : g_WH) + (size_t)(k0 + r)*D_ + c*8);
    }
    asm volatile("cp.async.commit_group;\n" ::: "memory");
  };

  fill(0, 0);
  for (int s = 0; s < 16; ++s) {
    if (s + 1 < 16) {
      fill((s + 1) & 1, (s + 1)*32);
      asm volatile("cp.async.wait_group 1;\n" ::: "memory");
    } else {
      asm volatile("cp.async.wait_group 0;\n" ::: "memory");
    }
    __syncthreads();

    const char* S = smg + (s & 1)*GSTAGE;
    const unsigned sBase = smem_u32p(S);
    const int arow = wm*32 + (lane & 7) + tg1*8;

#pragma unroll
    for (int ks = 0; ks < 2; ++ks) {
      unsigned aH[2][4], aL[2][4];
#pragma unroll
      for (int mt = 0; mt < 2; ++mt) {
        const unsigned ar = sBase + (arow + mt*16)*80 + (ks*2 + tg2)*16;
        ldsm4(ar, aH[mt]);
        ldsm4(ar + 10240, aL[mt]);
      }
      const int brow = ks*16 + (lane & 7) + tg1*8;
#pragma unroll
      for (int jp = 0; jp < 4; ++jp) {
        const int c  = nh*8 + 2*jp + tg2;
        const int ph = (c & 8) | ((c & 7) ^ (brow & 7));
        const unsigned ba = sBase + 20480 + brow*256 + ph*16;
        unsigned bH[4], bL[4];
        ldsm4t(ba, bH);
        ldsm4t(ba + 8192, bL);
#pragma unroll
        for (int mt = 0; mt < 2; ++mt) {
          mma_bf16(acc[mt][2*jp    ], aH[mt], bH[0], bH[1]);
          mma_bf16(acc[mt][2*jp    ], aH[mt], bL[0], bL[1]);
          mma_bf16(acc[mt][2*jp    ], aL[mt], bH[0], bH[1]);
          mma_bf16(acc[mt][2*jp + 1], aH[mt], bH[2], bH[3]);
          mma_bf16(acc[mt][2*jp + 1], aH[mt], bL[2], bL[3]);
          mma_bf16(acc[mt][2*jp + 1], aL[mt], bH[2], bH[3]);
        }
      }
    }
    __syncthreads();
  }

  // ---- fused epilogue: stage y to smem, +bias, row L2 norm, write q ----
  float* y       = (float*)smg;            // [128][129]
  float* partial = y + 128*129;            // [128][2]
  float* inorm   = partial + 256;          // [128]
#pragma unroll
  for (int mt = 0; mt < 2; ++mt) {
    const int row = wm*32 + mt*16 + g;
#pragma unroll
    for (int nt = 0; nt < 8; ++nt) {
      const int col = nh*64 + nt*8 + 2*tig;
      y[ row     *129 + col    ] = acc[mt][nt][0];
      y[ row     *129 + col + 1] = acc[mt][nt][1];
      y[(row + 8)*129 + col    ] = acc[mt][nt][2];
      y[(row + 8)*129 + col + 1] = acc[mt][nt][3];
    }
  }
  __syncthreads();
  {
    const int r = tid >> 1, hf = tid & 1;
    float ssum = 0.f;
#pragma unroll 8
    for (int d = hf*64; d < hf*64 + 64; ++d) {
      const float v = y[r*129 + d] + bias[d];
      y[r*129 + d] = v;
      ssum += v*v;
    }
    partial[r*2 + hf] = ssum;
  }
  __syncthreads();
  if (tid < 128)
    inorm[tid] = 1.0f / fmaxf(sqrtf(partial[tid*2] + partial[tid*2 + 1]), 1e-12f);
  __syncthreads();
  for (int i = tid; i < 128*128; i += 256) {
    const int rr = i >> 7, d = i & 127;
    const int m  = m0 + rr;
    const int bn = m / 20, t = m - bn*20;
    const int bq = bn / N_, n = bn - bq*N_;
    const float v = y[rr*129 + d] * inorm[rr];
    const size_t qi = ((size_t)(bq*T_ + t)*N_ + n)*D_ + d;
    g_qA[qi]  = v;
    g_qbf[qi] = __float2bfloat16_rn(v);
  }
}

// =============================================================================
// Kernel Q: transpose q to output layout (B, d, T, N). (unchanged)
// =============================================================================
#define SMEM_Q_BYTES (N_*129*sizeof(float))

__global__ __launch_bounds__(256) void kQ(float* __restrict__ qout) {
  extern __shared__ float sq[];            // [n][d] stride 129
  const int t = blockIdx.x, b = blockIdx.y, tid = threadIdx.x;
  const float* src = g_qA + ((size_t)(b*T_ + t)*N_)*D_;
  for (int i = tid; i < N_*D_; i += 256) {
    const int n = i >> 7, d = i & 127;
    sq[n*129 + d] = src[i];
  }
  __syncthreads();
  for (int i = tid; i < N_*D_; i += 256) {
    const int d = i / N_, n = i - d*N_;
    qout[((size_t)(b*D_ + d)*T_ + t)*N_ + n] = sq[n*129 + d];
  }
}

// =============================================================================
// Kernel B v2: affinity + palindrome softmax on tensor cores (plain bf16).
// CTA per (b,t), 448 thr (14 warps, warp = one 16-row m-tile, rows padded 224).
// Both operands [row][k] bf16, xor-swizzled; B frags via non-trans ldsm4.
// A frags preloaded to regs; 7 n-chunks x 8 k-steps. Fused exp + row sums
// (from regs) + col sums (from smem) + bf16 P writes (fwd and transposed bwd).
// =============================================================================
#define KB_A_OFF 0
#define KB_B_OFF 57344                      // 224 rows x 256 B
#define KB_SM_OFF 114688
#define KB_SSTR 232                         // Sm bf16 col stride
#define SMEM_B2_BYTES (KB_SM_OFF + 224*KB_SSTR*2)   // 218624

__global__ __launch_bounds__(448, 1) void kB() {
  extern __shared__ char smb[];
  __shared__ float rinvA[224], cinvA[224];

  const int t = blockIdx.x, b = blockIdx.y, tid = threadIdx.x;
  const int lane = tid & 31, w = tid >> 5;
  const int g = lane >> 2, tig = lane & 3;

  // zero pad rows 196..223 of A and B regions (448 float4 each)
  {
    float4 z = make_float4(0.f, 0.f, 0.f, 0.f);
    ((float4*)(smb + KB_A_OFF + 196*256))[tid] = z;
    ((float4*)(smb + KB_B_OFF + 196*256))[tid] = z;
  }
  // fill A (= q[t]) and B (= q[t+1]) with xor swizzle
  const __nv_bfloat16* Qa = g_qbf + ((size_t)(b*T_ + t    )*N_)*D_;
  const __nv_bfloat16* Qb = g_qbf + ((size_t)(b*T_ + t + 1)*N_)*D_;
  for (int idx = tid; idx < 196*16; idx += 448) {
    const int r = idx >> 4, c = idx & 15;
    const int ph = ((c & 7) ^ (r & 7)) | (c & 8);
    cpa16(smb + KB_A_OFF + r*256 + ph*16, Qa + (size_t)r*D_ + c*8);
    cpa16(smb + KB_B_OFF + r*256 + ph*16, Qb + (size_t)r*D_ + c*8);
  }
  asm volatile("cp.async.commit_group;\n" ::: "memory");
  asm volatile("cp.async.wait_group 0;\n" ::: "memory");
  __syncthreads();

  // preload A frags: warp w owns rows 16w..16w+15
  unsigned aF[8][4];
  {
    const unsigned aBase = smem_u32p(smb + KB_A_OFF);
    const int r = w*16 + (lane & 7) + ((lane >> 3) & 1)*8;
#pragma unroll
    for (int ks = 0; ks < 8; ++ks) {
      const int c  = 2*ks + ((lane >> 4) & 1);
      const int ph = ((c & 7) ^ (r & 7)) | (c & 8);
      ldsm4(smem_u32p(smb + KB_A_OFF) + r*256 + ph*16, aF[ks]);
      (void)aBase;
    }
  }

  const unsigned bBase = smem_u32p(smb + KB_B_OFF);
  __nv_bfloat16* Sm = (__nv_bfloat16*)(smb + KB_SM_OFF);
  const int m0r = w*16 + g;                 // rows m0r, m0r+8
  float rsum0 = 0.f, rsum1 = 0.f;

  // B frag lane addressing: bit4 -> row+8 (n-tile), bit3 -> k chunk hi
  const int brlo = (lane & 7) + ((lane >> 4) & 1)*8;
  const int bchi = (lane >> 3) & 1;

  for (int ch = 0; ch < 7; ++ch) {
    float acc[4][4];
#pragma unroll
    for (int nt = 0; nt < 4; ++nt)
#pragma unroll
      for (int j = 0; j < 4; ++j) acc[nt][j] = 0.f;

#pragma unroll
    for (int ks = 0; ks < 8; ++ks) {
#pragma unroll
      for (int half = 0; half < 2; ++half) {
        const int r  = ch*32 + half*16 + brlo;
        const int c  = 2*ks + bchi;
        const int ph = ((c & 7) ^ (r & 7)) | (c & 8);
        unsigned bf[4];
        ldsm4(bBase + r*256 + ph*16, bf);
        mma_bf16(acc[half*2    ], aF[ks], bf[0], bf[1]);
        mma_bf16(acc[half*2 + 1], aF[ks], bf[2], bf[3]);
      }
    }
    // exp + masked row partials + stage to Sm
#pragma unroll
    for (int nt = 0; nt < 4; ++nt) {
      const int col = ch*32 + nt*8 + 2*tig;
      const float e0 = __expf(acc[nt][0]*INV_TEMP);
      const float e1 = __expf(acc[nt][1]*INV_TEMP);
      const float e2 = __expf(acc[nt][2]*INV_TEMP);
      const float e3 = __expf(acc[nt][3]*INV_TEMP);
      if (col     < N_) { rsum0 += e0; rsum1 += e2; }
      if (col + 1 < N_) { rsum0 += e1; rsum1 += e3; }
      *(__nv_bfloat162*)(Sm + (size_t)m0r*KB_SSTR + col) =
          __nv_bfloat162(__float2bfloat16_rn(e0), __float2bfloat16_rn(e1));
      *(__nv_bfloat162*)(Sm + (size_t)(m0r + 8)*KB_SSTR + col) =
          __nv_bfloat162(__float2bfloat16_rn(e2), __float2bfloat16_rn(e3));
    }
  }
  // complete row sums over tig quad
  rsum0 += __shfl_xor_sync(0xffffffffu, rsum0, 1);
  rsum0 += __shfl_xor_sync(0xffffffffu, rsum0, 2);
  rsum1 += __shfl_xor_sync(0xffffffffu, rsum1, 1);
  rsum1 += __shfl_xor_sync(0xffffffffu, rsum1, 2);
  if (tig == 0) {
    rinvA[m0r]     = 1.0f / rsum0;
    rinvA[m0r + 8] = 1.0f / rsum1;
  }
  __syncthreads();
  // col sums from Sm (rows < 196 only): 2 threads per col
  {
    const int col = tid >> 1, r0 = (tid & 1)*98;
    float cs = 0.f;
    for (int r = r0; r < r0 + 98; ++r)
      cs += __bfloat162float(Sm[(size_t)r*KB_SSTR + col]);
    cs += __shfl_xor_sync(0xffffffffu, cs, 1);
    if ((tid & 1) == 0) cinvA[col] = 1.0f / cs;
  }
  __syncthreads();
  // write Pf and Pb (bf16, pads zeroed)
  __nv_bfloat16* Pf = g_P + (size_t)(b*S_ + t       )*MP2_;
  __nv_bfloat16* Pb = g_P + (size_t)(b*S_ + (37 - t))*MP2_;
  for (int idx = tid; idx < 224*112; idx += 448) {
    const int r = idx / 112, m2 = (idx - r*112)*2;
    float f0 = 0.f, f1 = 0.f, p0 = 0.f, p1 = 0.f;
    if (r < N_) {
      const float ri = rinvA[r], ci = cinvA[r];
      if (m2 < N_) {
        f0 = __bfloat162float(Sm[(size_t)r*KB_SSTR + m2]) * ri;
        p0 = __bfloat162float(Sm[(size_t)m2*KB_SSTR + r]) * ci;
      }
      if (m2 + 1 < N_) {
        f1 = __bfloat162float(Sm[(size_t)r*KB_SSTR + m2 + 1]) * ri;
        p1 = __bfloat162float(Sm[(size_t)(m2 + 1)*KB_SSTR + r]) * ci;
      }
    }
    *(__nv_bfloat162*)(Pf + (size_t)r*NP_ + m2) =
        __nv_bfloat162(__float2bfloat16_rn(f0), __float2bfloat16_rn(f1));
    *(__nv_bfloat162*)(Pb + (size_t)r*NP_ + m2) =
        __nv_bfloat162(__float2bfloat16_rn(p0), __float2bfloat16_rn(p1));
  }
}

// =============================================================================
// Kernel C: product-tree GEMM, pure bf16 whole-tile smem. (unchanged R6)
// =============================================================================
#define KS_ 13
#define AROWB 416
#define ABYTES (112*AROWB)
#define BROWB 128
#define BBYTES (208*BROWB)
#define SMEM_C_BYTES (ABYTES + BBYTES)

__device__ __forceinline__ int aphys(int c, int r) {
  return (c < 24) ? ((c & ~7) | ((c & 7) ^ (r & 7))) : c;
}

__global__ __launch_bounds__(224, 3) void kC(int level, int Lin, int Lout, int npairs) {
  extern __shared__ char smc[];

  const __nv_bfloat16* src; __nv_bfloat16* dst;
  switch (level) {
    case 0:  src = g_P;  dst = g_b1; break;
    case 1:  src = g_b1; dst = g_b2; break;
    case 2:  src = g_b2; dst = g_b1; break;
    case 3:  src = g_b1; dst = g_b2; break;
    case 4:  src = g_b2; dst = g_b1; break;
    default: src = g_b1; dst = 0;    break;
  }

  const int xt  = blockIdx.x;
  const int p   = blockIdx.y;
  const int b   = blockIdx.z;
  const int tid = threadIdx.x;

  if (p >= npairs) {
    const float4* Sg = (const float4*)(src + ((size_t)b*Lin + (Lin - 1))*MP2_);
    float4*       Dg = (float4*)(dst + ((size_t)b*Lout + npairs)*MP2_);
    const int q = MP2_*2/16/8;
    for (int i = xt*q + tid; i < (xt + 1)*q; i += 224) Dg[i] = Sg[i];
    return;
  }

  const int mt = xt & 1, ct = xt >> 1;
  const int row0 = mt * 112;
  const int col0 = ct * 56;

  const char* Am = (const char*)(src + ((size_t)b*Lin + 2*p + 1)*MP2_);
  const char* Bm = (const char*)(src + ((size_t)b*Lin + 2*p    )*MP2_);

  {
    const int r  = tid >> 1;
    const int cb = tid & 1;
#pragma unroll
    for (int i = 0; i < 13; ++i) {
      const int c = cb + 2*i;
      cpa16(smc + r*AROWB + aphys(c, r)*16, Am + (size_t)(row0 + r)*448 + c*16);
    }
    for (int idx = tid; idx < 208*8; idx += 224) {
      const int rr = idx >> 3, c = idx & 7;
      cpa16(smc + ABYTES + rr*BROWB + (c ^ (rr & 7))*16,
            Bm + (size_t)rr*448 + col0*2 + c*16);
    }
    asm volatile("cp.async.commit_group;\n" ::: "memory");
    asm volatile("cp.async.wait_group 0;\n" ::: "memory");
  }
  __syncthreads();

  const int lane = tid & 31;
  const int w    = tid >> 5;
  const int tg1  = (lane >> 3) & 1;
  const int tg2  = (lane >> 4) & 1;
  const int g    = lane >> 2;
  const int tig  = lane & 3;

  const int arow = w*16 + (lane & 7) + tg1*8;
  const unsigned aRowAddr = smem_u32p(smc) + arow*AROWB;
  const unsigned bBase    = smem_u32p(smc + ABYTES);
  const int bkoff = (lane & 7) + tg1*8;
  const int bk2off = ((lane & 15) & 7) + (((lane & 15) >> 3) & 1)*8;

  float acc[7][4];
#pragma unroll
  for (int nt = 0; nt < 7; ++nt)
#pragma unroll
    for (int j = 0; j < 4; ++j) acc[nt][j] = 0.f;

#pragma unroll
  for (int kk = 0; kk < KS_; ++kk) {
    unsigned aH[4];
    {
      const int ca = kk*2 + tg2;
      ldsm4(aRowAddr + aphys(ca, arow)*16, aH);
    }
    const int brow = kk*16 + bkoff;
    const int ksw  = brow & 7;
    const unsigned bRow = bBase + brow*BROWB;
#pragma unroll
    for (int jp = 0; jp < 3; ++jp) {
      const int cH = 2*jp + tg2;
      unsigned bb[4];
      ldsm4t(bRow + ((cH ^ ksw) << 4), bb);
      mma_bf16(acc[2*jp    ], aH, bb[0], bb[1]);
      mma_bf16(acc[2*jp + 1], aH, bb[2], bb[3]);
    }
    {
      const int r2  = kk*16 + bk2off;
      unsigned b2[2];
      ldsm2t(bBase + r2*BROWB + ((6 ^ (r2 & 7)) << 4), b2);
      mma_bf16(acc[6], aH, b2[0], b2[1]);
    }
  }

  const int r0g = row0 + w*16 + g;
  if (level < 5) {
    __nv_bfloat16* Cm = dst + ((size_t)b*Lout + p)*MP2_;
#pragma unroll
    for (int nt = 0; nt < 7; ++nt) {
      const int col = col0 + nt*8 + 2*tig;
      *(__nv_bfloat162*)(Cm + (size_t)r0g*NP_ + col) =
          __nv_bfloat162(__float2bfloat16_rn(acc[nt][0]), __float2bfloat16_rn(acc[nt][1]));
      *(__nv_bfloat162*)(Cm + (size_t)(r0g + 8)*NP_ + col) =
          __nv_bfloat162(__float2bfloat16_rn(acc[nt][2]), __float2bfloat16_rn(acc[nt][3]));
    }
  } else {
    float* Cm = g_At + (size_t)b*MP2_;
#pragma unroll
    for (int nt = 0; nt < 7; ++nt) {
      const int col = col0 + nt*8 + 2*tig;
      *(float2*)(Cm + (size_t)r0g*NP_ + col)       = make_float2(acc[nt][0], acc[nt][1]);
      *(float2*)(Cm + (size_t)(r0g + 8)*NP_ + col) = make_float2(acc[nt][2], acc[nt][3]);
    }
  }
}

// =============================================================================
// Kernel D/E: loss + acc. (unchanged)
// =============================================================================
__global__ void kD() {
  __shared__ float sl[N_], sa[N_];
  const int b = blockIdx.x, n = threadIdx.x;
  const float* row = g_At + (size_t)b*MP2_ + (size_t)n*NP_;
  float rs = 0.f, best = -1.f;
  int bi = 0;
  for (int m = 0; m < N_; ++m) {
    const float v = row[m];
    rs += v;
    if (v > best) { best = v; bi = m; }
  }
  const float diag = row[n];
  sl[n] = logf(rs + (float)N_ * EPS_) - logf(diag + EPS_);
  sa[n] = (bi == n) ? 1.f : 0.f;
  __syncthreads();
  if (n == 0) {
    float L = 0.f, A = 0.f;
    for (int i = 0; i < N_; ++i) { L += sl[i]; A += sa[i]; }
    g_partial[b]      = L;
    g_partial[B_ + b] = A;
  }
}

__global__ void kE(float* out, int out_size) {
  float L = 0.f, A = 0.f;
  for (int b = 0; b < B_; ++b) { L += g_partial[b]; A += g_partial[B_ + b]; }
  const float inv = 1.0f / (float)(B_ * N_);
  if (out_size > QSIZE)     out[QSIZE]     = L * inv;
  if (out_size > QSIZE + 1) out[QSIZE + 1] = A * inv;
}

// =============================================================================
extern "C" void kernel_launch(void* const* d_in, const int* in_sizes, int n_in,
                              void* d_out, int out_size) {
  const float* maps = (const float*)d_in[0];
  const float* W    = (const float*)d_in[1];
  const float* bias = (const float*)d_in[2];
  float* out = (float*)d_out;

  cudaFuncSetAttribute(kP, cudaFuncAttributeMaxDynamicSharedMemorySize, (int)SMEM_P_BYTES);
  cudaFuncSetAttribute(kG, cudaFuncAttributeMaxDynamicSharedMemorySize, (int)SMEM_G_BYTES);
  cudaFuncSetAttribute(kQ, cudaFuncAttributeMaxDynamicSharedMemorySize, (int)SMEM_Q_BYTES);
  cudaFuncSetAttribute(kB, cudaFuncAttributeMaxDynamicSharedMemorySize, (int)SMEM_B2_BYTES);
  cudaFuncSetAttribute(kC, cudaFuncAttributeMaxDynamicSharedMemorySize, (int)SMEM_C_BYTES);

  kP<<<B_*N_, 128, SMEM_P_BYTES>>>(maps);
  kW<<<256, 256>>>(W);
  kG<<<M_/128, 256, SMEM_G_BYTES>>>(bias);
  kB<<<dim3(T_ - 1, B_), 448, SMEM_B2_BYTES>>>();
  kQ<<<dim3(T_, B_), 256, SMEM_Q_BYTES>>>(out);

  // product tree: 38 -> 19 -> 10 -> 5 -> 3 -> 2 -> 1
  const int lv[6][5] = {
    {0, 38, 19, 19, 0},
    {1, 19, 10,  9, 1},
    {2, 10,  5,  5, 0},
    {3,  5,  3,  2, 1},
    {4,  3,  2,  1, 1},
    {5,  2,  1,  1, 0},
  };
  for (int l = 0; l < 6; ++l) {
    kC<<<dim3(8, lv[l][3] + lv[l][4], B_), 224, SMEM_C_BYTES>>>(
        lv[l][0], lv[l][1], lv[l][2], lv[l][3]);
  }

  kD<<<B_, N_>>>();
  kE<<<1, 1>>>(out, out_size);
}

// round 9
// speedup vs baseline: 4.0941x; 1.0584x over previous
#include <cuda_runtime.h>
#include <cuda_bf16.h>
#include <math.h>

#define B_ 16
#define N_ 196
#define C_ 512
#define T_ 20
#define D_ 128
#define S_ 38
#define NP_ 224                    // padded row/col stride for chain matrices
#define MP2_ (NP_*NP_)             // 50176 elems per padded matrix
#define M_ 62720                   // B*N*T rows of the head GEMM (=490*128)
#define QSIZE 8028160              // B*D*T*N
#define INV_TEMP (1.0f/0.07f)
#define EPS_ 1e-20f

// ---------------- scratch (static device globals; no allocation) ----------------
__device__ float g_qA[B_*T_*N_*D_];                                  // [b][t][n][d] fp32
__device__ __align__(256) __nv_bfloat16 g_qbf[B_*T_*N_*D_];          // bf16 copy of q
__device__ __align__(256) __nv_bfloat16 g_qpH[(size_t)M_*C_];        // pooled acts hi
__device__ __align__(256) __nv_bfloat16 g_qpL[(size_t)M_*C_];        // pooled acts lo
__device__ __align__(256) __nv_bfloat16 g_WH[C_*D_];                 // W hi
__device__ __align__(256) __nv_bfloat16 g_WL[C_*D_];                 // W lo
__device__ __align__(256) __nv_bfloat16 g_P [(size_t)B_*S_*MP2_ + 256];
__device__ __align__(256) __nv_bfloat16 g_b1[(size_t)B_*13*MP2_ + 256];
__device__ __align__(256) __nv_bfloat16 g_b2[(size_t)B_*5*MP2_ + 256];
__device__ float g_At[(size_t)B_*MP2_];                              // final product fp32
__device__ float g_partial[2*B_];

// ---------------- mma / ldmatrix / cp.async helpers -------------------------
__device__ __forceinline__ void cpa16(void* dst_smem, const void* src) {
  unsigned d = (unsigned)__cvta_generic_to_shared(dst_smem);
  asm volatile("cp.async.cg.shared.global [%0], [%1], 16;\n" :: "r"(d), "l"(src));
}
__device__ __forceinline__ unsigned smem_u32p(const void* p) {
  return (unsigned)__cvta_generic_to_shared(p);
}
__device__ __forceinline__ void ldsm4(unsigned addr, unsigned* r) {
  asm volatile("ldmatrix.sync.aligned.m8n8.x4.shared.b16 {%0,%1,%2,%3}, [%4];\n"
               : "=r"(r[0]), "=r"(r[1]), "=r"(r[2]), "=r"(r[3]) : "r"(addr));
}
__device__ __forceinline__ void ldsm4t(unsigned addr, unsigned* r) {
  asm volatile("ldmatrix.sync.aligned.m8n8.x4.trans.shared.b16 {%0,%1,%2,%3}, [%4];\n"
               : "=r"(r[0]), "=r"(r[1]), "=r"(r[2]), "=r"(r[3]) : "r"(addr));
}
__device__ __forceinline__ void mma_bf16(float* d, const unsigned* a,
                                         unsigned b0, unsigned b1) {
  asm volatile(
      "mma.sync.aligned.m16n8k16.row.col.f32.bf16.bf16.f32 "
      "{%0,%1,%2,%3}, {%4,%5,%6,%7}, {%8,%9}, {%0,%1,%2,%3};\n"
      : "+f"(d[0]), "+f"(d[1]), "+f"(d[2]), "+f"(d[3])
      : "r"(a[0]), "r"(a[1]), "r"(a[2]), "r"(a[3]), "r"(b0), "r"(b1));
}
__device__ __forceinline__ int aphys(int c, int r) {
  return (c < 24) ? ((c & ~7) | ((c & 7) ^ (r & 7))) : c;
}

// =============================================================================
// Kernel P: spatial pool + bf16 hi/lo split of pooled activations.
// =============================================================================
#define SMEM_P_BYTES (C_*21*sizeof(float))

__global__ __launch_bounds__(256) void kP(const float* __restrict__ maps) {
  extern __shared__ float qp[];             // [c][t] stride 21
  const int bn = blockIdx.x, tid = threadIdx.x;
  const float4* src = reinterpret_cast<const float4*>(maps) + (size_t)bn * (C_*T_);
  for (int i = tid; i < C_*T_; i += 256) {
    float4 v = src[i];
    const int c = i / 20, t = i - c*20;
    qp[c*21 + t] = (v.x + v.y + v.z + v.w) * 0.25f;
  }
  __syncthreads();
  __nv_bfloat16* AH = g_qpH + (size_t)bn*20*C_;
  __nv_bfloat16* AL = g_qpL + (size_t)bn*20*C_;
  for (int i = tid; i < 20*C_; i += 256) {
    const int t = i >> 9, c = i & 511;
    const float x = qp[c*21 + t];
    const __nv_bfloat16 h = __float2bfloat16_rn(x);
    AH[t*C_ + c] = h;
    AL[t*C_ + c] = __float2bfloat16_rn(x - __bfloat162float(h));
  }
}

// W split (512x128 -> H/L planes)
__global__ void kW(const float* __restrict__ W) {
  const int i = blockIdx.x*256 + threadIdx.x;   // grid 256 x 256 = 65536
  const float x = W[i];
  const __nv_bfloat16 h = __float2bfloat16_rn(x);
  g_WH[i] = h;
  g_WL[i] = __float2bfloat16_rn(x - __bfloat162float(h));
}

// =============================================================================
// Kernel G: head GEMM on tensor cores (3-pass bf16 split, fused bias+norm).
// =============================================================================
#define GSTAGE 36864
#define SMEM_G_BYTES (2*GSTAGE)             // 73728

__global__ __launch_bounds__(256, 2) void kG(const float* __restrict__ bias) {
  extern __shared__ char smg[];
  const int m0  = blockIdx.x * 128;
  const int tid = threadIdx.x;
  const int lane = tid & 31, w = tid >> 5;
  const int wm = w & 3, nh = w >> 2;
  const int g = lane >> 2, tig = lane & 3;
  const int tg1 = (lane >> 3) & 1, tg2 = (lane >> 4) & 1;

  const __nv_bfloat16* AmH = g_qpH + (size_t)m0*C_;
  const __nv_bfloat16* AmL = g_qpL + (size_t)m0*C_;

  float acc[2][8][4];
#pragma unroll
  for (int mt = 0; mt < 2; ++mt)
#pragma unroll
    for (int nt = 0; nt < 8; ++nt)
#pragma unroll
      for (int j = 0; j < 4; ++j) acc[mt][nt][j] = 0.f;

  auto fill = [&](int stg, int k0) {
    char* S = smg + stg*GSTAGE;
#pragma unroll
    for (int i = 0; i < 4; ++i) {
      const int idx = tid + i*256;
      const int r = idx >> 3, z = idx & 7;
      const int pl = z >> 2, c = z & 3;
      cpa16(S + pl*10240 + r*80 + c*16,
            (pl ? AmL : AmH) + (size_t)r*C_ + k0 + c*8);
    }
#pragma unroll
    for (int i = 0; i < 4; ++i) {
      const int idx = tid + i*256;
      const int r = idx >> 5, z = idx & 31;
      const int pl = z >> 4, c = z & 15;
      const int ph = (c & 8) | ((c & 7) ^ (r & 7));
      cpa16(S + 20480 + pl*8192 + r*256 + ph*16,
            (pl ? g_WL : g_WH) + (size_t)(k0 + r)*D_ + c*8);
    }
    asm volatile("cp.async.commit_group;\n" ::: "memory");
  };

  fill(0, 0);
  for (int s = 0; s < 16; ++s) {
    if (s + 1 < 16) {
      fill((s + 1) & 1, (s + 1)*32);
      asm volatile("cp.async.wait_group 1;\n" ::: "memory");
    } else {
      asm volatile("cp.async.wait_group 0;\n" ::: "memory");
    }
    __syncthreads();

    const char* S = smg + (s & 1)*GSTAGE;
    const unsigned sBase = smem_u32p(S);
    const int arow = wm*32 + (lane & 7) + tg1*8;

#pragma unroll
    for (int ks = 0; ks < 2; ++ks) {
      unsigned aH[2][4], aL[2][4];
#pragma unroll
      for (int mt = 0; mt < 2; ++mt) {
        const unsigned ar = sBase + (arow + mt*16)*80 + (ks*2 + tg2)*16;
        ldsm4(ar, aH[mt]);
        ldsm4(ar + 10240, aL[mt]);
      }
      const int brow = ks*16 + (lane & 7) + tg1*8;
#pragma unroll
      for (int jp = 0; jp < 4; ++jp) {
        const int c  = nh*8 + 2*jp + tg2;
        const int ph = (c & 8) | ((c & 7) ^ (brow & 7));
        const unsigned ba = sBase + 20480 + brow*256 + ph*16;
        unsigned bH[4], bL[4];
        ldsm4t(ba, bH);
        ldsm4t(ba + 8192, bL);
#pragma unroll
        for (int mt = 0; mt < 2; ++mt) {
          mma_bf16(acc[mt][2*jp    ], aH[mt], bH[0], bH[1]);
          mma_bf16(acc[mt][2*jp    ], aH[mt], bL[0], bL[1]);
          mma_bf16(acc[mt][2*jp    ], aL[mt], bH[0], bH[1]);
          mma_bf16(acc[mt][2*jp + 1], aH[mt], bH[2], bH[3]);
          mma_bf16(acc[mt][2*jp + 1], aH[mt], bL[2], bL[3]);
          mma_bf16(acc[mt][2*jp + 1], aL[mt], bH[2], bH[3]);
        }
      }
    }
    __syncthreads();
  }

  // ---- fused epilogue: stage y to smem, +bias, row L2 norm, write q ----
  float* y       = (float*)smg;            // [128][129]
  float* partial = y + 128*129;            // [128][2]
  float* inorm   = partial + 256;          // [128]
#pragma unroll
  for (int mt = 0; mt < 2; ++mt) {
    const int row = wm*32 + mt*16 + g;
#pragma unroll
    for (int nt = 0; nt < 8; ++nt) {
      const int col = nh*64 + nt*8 + 2*tig;
      y[ row     *129 + col    ] = acc[mt][nt][0];
      y[ row     *129 + col + 1] = acc[mt][nt][1];
      y[(row + 8)*129 + col    ] = acc[mt][nt][2];
      y[(row + 8)*129 + col + 1] = acc[mt][nt][3];
    }
  }
  __syncthreads();
  {
    const int r = tid >> 1, hf = tid & 1;
    float ssum = 0.f;
#pragma unroll 8
    for (int d = hf*64; d < hf*64 + 64; ++d) {
      const float v = y[r*129 + d] + bias[d];
      y[r*129 + d] = v;
      ssum += v*v;
    }
    partial[r*2 + hf] = ssum;
  }
  __syncthreads();
  if (tid < 128)
    inorm[tid] = 1.0f / fmaxf(sqrtf(partial[tid*2] + partial[tid*2 + 1]), 1e-12f);
  __syncthreads();
  for (int i = tid; i < 128*128; i += 256) {
    const int rr = i >> 7, d = i & 127;
    const int m  = m0 + rr;
    const int bn = m / 20, t = m - bn*20;
    const int bq = bn / N_, n = bn - bq*N_;
    const float v = y[rr*129 + d] * inorm[rr];
    const size_t qi = ((size_t)(bq*T_ + t)*N_ + n)*D_ + d;
    g_qA[qi]  = v;
    g_qbf[qi] = __float2bfloat16_rn(v);
  }
}

// =============================================================================
// Kernel Q: transpose q to output layout (B, d, T, N). (unchanged)
// =============================================================================
#define SMEM_Q_BYTES (N_*129*sizeof(float))

__global__ __launch_bounds__(256) void kQ(float* __restrict__ qout) {
  extern __shared__ float sq[];            // [n][d] stride 129
  const int t = blockIdx.x, b = blockIdx.y, tid = threadIdx.x;
  const float* src = g_qA + ((size_t)(b*T_ + t)*N_)*D_;
  for (int i = tid; i < N_*D_; i += 256) {
    const int n = i >> 7, d = i & 127;
    sq[n*129 + d] = src[i];
  }
  __syncthreads();
  for (int i = tid; i < N_*D_; i += 256) {
    const int d = i / N_, n = i - d*N_;
    qout[((size_t)(b*D_ + d)*T_ + t)*N_ + n] = sq[n*129 + d];
  }
}

// =============================================================================
// Kernel B: affinity + palindrome softmax on tensor cores. (unchanged R8)
// =============================================================================
#define KB_A_OFF 0
#define KB_B_OFF 57344                      // 224 rows x 256 B
#define KB_SM_OFF 114688
#define KB_SSTR 232                         // Sm bf16 col stride
#define SMEM_B2_BYTES (KB_SM_OFF + 224*KB_SSTR*2)   // 218624

__global__ __launch_bounds__(448, 1) void kB() {
  extern __shared__ char smb[];
  __shared__ float rinvA[224], cinvA[224];

  const int t = blockIdx.x, b = blockIdx.y, tid = threadIdx.x;
  const int lane = tid & 31, w = tid >> 5;
  const int g = lane >> 2, tig = lane & 3;

  {
    float4 z = make_float4(0.f, 0.f, 0.f, 0.f);
    ((float4*)(smb + KB_A_OFF + 196*256))[tid] = z;
    ((float4*)(smb + KB_B_OFF + 196*256))[tid] = z;
  }
  const __nv_bfloat16* Qa = g_qbf + ((size_t)(b*T_ + t    )*N_)*D_;
  const __nv_bfloat16* Qb = g_qbf + ((size_t)(b*T_ + t + 1)*N_)*D_;
  for (int idx = tid; idx < 196*16; idx += 448) {
    const int r = idx >> 4, c = idx & 15;
    const int ph = ((c & 7) ^ (r & 7)) | (c & 8);
    cpa16(smb + KB_A_OFF + r*256 + ph*16, Qa + (size_t)r*D_ + c*8);
    cpa16(smb + KB_B_OFF + r*256 + ph*16, Qb + (size_t)r*D_ + c*8);
  }
  asm volatile("cp.async.commit_group;\n" ::: "memory");
  asm volatile("cp.async.wait_group 0;\n" ::: "memory");
  __syncthreads();

  unsigned aF[8][4];
  {
    const int r = w*16 + (lane & 7) + ((lane >> 3) & 1)*8;
#pragma unroll
    for (int ks = 0; ks < 8; ++ks) {
      const int c  = 2*ks + ((lane >> 4) & 1);
      const int ph = ((c & 7) ^ (r & 7)) | (c & 8);
      ldsm4(smem_u32p(smb + KB_A_OFF) + r*256 + ph*16, aF[ks]);
    }
  }

  const unsigned bBase = smem_u32p(smb + KB_B_OFF);
  __nv_bfloat16* Sm = (__nv_bfloat16*)(smb + KB_SM_OFF);
  const int m0r = w*16 + g;
  float rsum0 = 0.f, rsum1 = 0.f;

  const int brlo = (lane & 7) + ((lane >> 4) & 1)*8;
  const int bchi = (lane >> 3) & 1;

  for (int ch = 0; ch < 7; ++ch) {
    float acc[4][4];
#pragma unroll
    for (int nt = 0; nt < 4; ++nt)
#pragma unroll
      for (int j = 0; j < 4; ++j) acc[nt][j] = 0.f;

#pragma unroll
    for (int ks = 0; ks < 8; ++ks) {
#pragma unroll
      for (int half = 0; half < 2; ++half) {
        const int r  = ch*32 + half*16 + brlo;
        const int c  = 2*ks + bchi;
        const int ph = ((c & 7) ^ (r & 7)) | (c & 8);
        unsigned bf[4];
        ldsm4(bBase + r*256 + ph*16, bf);
        mma_bf16(acc[half*2    ], aF[ks], bf[0], bf[1]);
        mma_bf16(acc[half*2 + 1], aF[ks], bf[2], bf[3]);
      }
    }
#pragma unroll
    for (int nt = 0; nt < 4; ++nt) {
      const int col = ch*32 + nt*8 + 2*tig;
      const float e0 = __expf(acc[nt][0]*INV_TEMP);
      const float e1 = __expf(acc[nt][1]*INV_TEMP);
      const float e2 = __expf(acc[nt][2]*INV_TEMP);
      const float e3 = __expf(acc[nt][3]*INV_TEMP);
      if (col     < N_) { rsum0 += e0; rsum1 += e2; }
      if (col + 1 < N_) { rsum0 += e1; rsum1 += e3; }
      *(__nv_bfloat162*)(Sm + (size_t)m0r*KB_SSTR + col) =
          __nv_bfloat162(__float2bfloat16_rn(e0), __float2bfloat16_rn(e1));
      *(__nv_bfloat162*)(Sm + (size_t)(m0r + 8)*KB_SSTR + col) =
          __nv_bfloat162(__float2bfloat16_rn(e2), __float2bfloat16_rn(e3));
    }
  }
  rsum0 += __shfl_xor_sync(0xffffffffu, rsum0, 1);
  rsum0 += __shfl_xor_sync(0xffffffffu, rsum0, 2);
  rsum1 += __shfl_xor_sync(0xffffffffu, rsum1, 1);
  rsum1 += __shfl_xor_sync(0xffffffffu, rsum1, 2);
  if (tig == 0) {
    rinvA[m0r]     = 1.0f / rsum0;
    rinvA[m0r + 8] = 1.0f / rsum1;
  }
  __syncthreads();
  {
    const int col = tid >> 1, r0 = (tid & 1)*98;
    float cs = 0.f;
    for (int r = r0; r < r0 + 98; ++r)
      cs += __bfloat162float(Sm[(size_t)r*KB_SSTR + col]);
    cs += __shfl_xor_sync(0xffffffffu, cs, 1);
    if ((tid & 1) == 0) cinvA[col] = 1.0f / cs;
  }
  __syncthreads();
  __nv_bfloat16* Pf = g_P + (size_t)(b*S_ + t       )*MP2_;
  __nv_bfloat16* Pb = g_P + (size_t)(b*S_ + (37 - t))*MP2_;
  for (int idx = tid; idx < 224*112; idx += 448) {
    const int r = idx / 112, m2 = (idx - r*112)*2;
    float f0 = 0.f, f1 = 0.f, p0 = 0.f, p1 = 0.f;
    if (r < N_) {
      const float ri = rinvA[r], ci = cinvA[r];
      if (m2 < N_) {
        f0 = __bfloat162float(Sm[(size_t)r*KB_SSTR + m2]) * ri;
        p0 = __bfloat162float(Sm[(size_t)m2*KB_SSTR + r]) * ci;
      }
      if (m2 + 1 < N_) {
        f1 = __bfloat162float(Sm[(size_t)r*KB_SSTR + m2 + 1]) * ri;
        p1 = __bfloat162float(Sm[(size_t)(m2 + 1)*KB_SSTR + r]) * ci;
      }
    }
    *(__nv_bfloat162*)(Pf + (size_t)r*NP_ + m2) =
        __nv_bfloat162(__float2bfloat16_rn(f0), __float2bfloat16_rn(f1));
    *(__nv_bfloat162*)(Pb + (size_t)r*NP_ + m2) =
        __nv_bfloat162(__float2bfloat16_rn(p0), __float2bfloat16_rn(p1));
  }
}

// =============================================================================
// Kernel T: fused triple-product tree level. out_p = src[3p+2]@src[3p+1]@src[3p]
// (cnt may be 2 -> single pair mul, or 1 -> copy). 4 levels: 38->13->5->2->1.
// CTA = 112 rows x full 224 cols, 224 thr (7 warps x 16 rows), 112 accs/thr.
// A-slot rows are warp-private -> intermediate M written back with no CTA sync;
// only the B-slot refill (A0) needs a barrier. K cropped to 208.
// =============================================================================
#define T_AROWB 416
#define T_ABYTES (112*T_AROWB)              // 46592
#define T_BROWB 512
#define T_BBYTES (208*T_BROWB)              // 106496
#define SMEM_T_BYTES (T_ABYTES + T_BBYTES)  // 153088

__global__ __launch_bounds__(224) void kT(int level, int Lin) {
  extern __shared__ char smt[];
  const int Lout = (Lin + 2) / 3;

  const __nv_bfloat16* src; __nv_bfloat16* dstb;
  switch (level) {
    case 0:  src = g_P;  dstb = g_b1; break;
    case 1:  src = g_b1; dstb = g_b2; break;
    case 2:  src = g_b2; dstb = g_b1; break;
    default: src = g_b1; dstb = 0;   break;   // level 3 -> fp32 g_At
  }

  const int tile = blockIdx.x;        // 0..1 row halves
  const int p    = blockIdx.y;
  const int b    = blockIdx.z;
  const int tid  = threadIdx.x;
  const int base = 3*p;
  const int rem  = Lin - base;
  const int cnt  = rem < 3 ? rem : 3;
  const int row0 = tile * 112;

  if (cnt == 1) {                     // carry: copy through
    const float4* Sg = (const float4*)(src + ((size_t)b*Lin + base)*MP2_);
    float4*       Dg = (float4*)(dstb + ((size_t)b*Lout + p)*MP2_);
    for (int i = tile*3136 + tid; i < (tile + 1)*3136; i += 224) Dg[i] = Sg[i];
    return;
  }

  const __nv_bfloat16* S0 = src + ((size_t)b*Lin + base    )*MP2_;
  const __nv_bfloat16* S1 = src + ((size_t)b*Lin + base + 1)*MP2_;
  const __nv_bfloat16* S2 = src + ((size_t)b*Lin + base + 2)*MP2_;

  const int lane = tid & 31, w = tid >> 5;
  const int tg1 = (lane >> 3) & 1, tg2 = (lane >> 4) & 1;
  const int g = lane >> 2, tig = lane & 3;
  const int arow  = w*16 + (lane & 7) + tg1*8;
  const int bkoff = (lane & 7) + tg1*8;
  const unsigned aBase = smem_u32p(smt);
  const unsigned bBase = smem_u32p(smt + T_ABYTES);

  auto fillA = [&](const __nv_bfloat16* Ms) {
    const char* Am = (const char*)Ms;
    const int r = tid >> 1, cb = tid & 1;
#pragma unroll
    for (int i = 0; i < 13; ++i) {
      const int c = cb + 2*i;
      cpa16(smt + r*T_AROWB + aphys(c, r)*16, Am + (size_t)(row0 + r)*448 + c*16);
    }
  };
  auto fillB = [&](const __nv_bfloat16* Ms) {
    const char* Bm = (const char*)Ms;
    for (int idx = tid; idx < 208*28; idx += 224) {
      const int r = idx / 28, c = idx - r*28;
      const int ph = (c & ~7) | ((c & 7) ^ (r & 7));
      cpa16(smt + T_ABYTES + r*T_BROWB + ph*16, Bm + (size_t)r*448 + c*16);
    }
  };

  float acc[28][4];
  auto mul = [&]() {
#pragma unroll
    for (int nt = 0; nt < 28; ++nt)
#pragma unroll
      for (int j = 0; j < 4; ++j) acc[nt][j] = 0.f;
#pragma unroll
    for (int kk = 0; kk < 13; ++kk) {
      unsigned aF[4];
      const int ca = kk*2 + tg2;
      ldsm4(aBase + arow*T_AROWB + aphys(ca, arow)*16, aF);
      const int brow = kk*16 + bkoff;
      const unsigned bRow = bBase + brow*T_BROWB;
      const int ksw = brow & 7;
#pragma unroll
      for (int jp = 0; jp < 14; ++jp) {
        const int cH = 2*jp + tg2;
        const int ph = (cH & ~7) | ((cH & 7) ^ ksw);
        unsigned bb[4];
        ldsm4t(bRow + ph*16, bb);
        mma_bf16(acc[2*jp    ], aF, bb[0], bb[1]);
        mma_bf16(acc[2*jp + 1], aF, bb[2], bb[3]);
      }
    }
  };

  // stage 1
  if (cnt == 3) { fillA(S2); fillB(S1); }
  else          { fillA(S1); fillB(S0); }
  asm volatile("cp.async.commit_group;\n" ::: "memory");
  asm volatile("cp.async.wait_group 0;\n" ::: "memory");
  __syncthreads();
  mul();

  if (cnt == 3) {
    // write M (bf16) into own-warp A-slot rows (cols 0..207)
    const int m0r = w*16 + g;
#pragma unroll
    for (int nt = 0; nt < 26; ++nt) {
      const int ph = aphys(nt, m0r);           // (m0r+8)&7 == m0r&7 -> same ph
      *(__nv_bfloat162*)(smt + m0r*T_AROWB + ph*16 + tig*4) =
          __nv_bfloat162(__float2bfloat16_rn(acc[nt][0]), __float2bfloat16_rn(acc[nt][1]));
      *(__nv_bfloat162*)(smt + (m0r + 8)*T_AROWB + ph*16 + tig*4) =
          __nv_bfloat162(__float2bfloat16_rn(acc[nt][2]), __float2bfloat16_rn(acc[nt][3]));
    }
    __syncthreads();                           // all warps done reading B (A1)
    fillB(S0);
    asm volatile("cp.async.commit_group;\n" ::: "memory");
    asm volatile("cp.async.wait_group 0;\n" ::: "memory");
    __syncthreads();
    mul();                                     // D = M @ A0
  }

  // store
  const int r0g = row0 + w*16 + g;
  if (level < 3) {
    __nv_bfloat16* Cm = dstb + ((size_t)b*Lout + p)*MP2_;
#pragma unroll
    for (int nt = 0; nt < 28; ++nt) {
      const int col = nt*8 + 2*tig;
      *(__nv_bfloat162*)(Cm + (size_t)r0g*NP_ + col) =
          __nv_bfloat162(__float2bfloat16_rn(acc[nt][0]), __float2bfloat16_rn(acc[nt][1]));
      *(__nv_bfloat162*)(Cm + (size_t)(r0g + 8)*NP_ + col) =
          __nv_bfloat162(__float2bfloat16_rn(acc[nt][2]), __float2bfloat16_rn(acc[nt][3]));
    }
  } else {
    float* Cm = g_At + (size_t)b*MP2_;
#pragma unroll
    for (int nt = 0; nt < 28; ++nt) {
      const int col = nt*8 + 2*tig;
      *(float2*)(Cm + (size_t)r0g*NP_ + col)       = make_float2(acc[nt][0], acc[nt][1]);
      *(float2*)(Cm + (size_t)(r0g + 8)*NP_ + col) = make_float2(acc[nt][2], acc[nt][3]);
    }
  }
}

// =============================================================================
// Kernel D: per-row loss/acc, smem-staged coalesced loads.
// =============================================================================
#define SMEM_D_BYTES (N_*197*sizeof(float))

__global__ __launch_bounds__(224) void kD() {
  extern __shared__ float sd[];              // [196][197]
  __shared__ float sl[N_], sa[N_];
  const int b = blockIdx.x, tid = threadIdx.x;
  const float* At = g_At + (size_t)b*MP2_;
  for (int idx = tid; idx < N_*N_; idx += 224) {
    const int r = idx / N_, m = idx - r*N_;
    sd[r*197 + m] = At[(size_t)r*NP_ + m];
  }
  __syncthreads();
  if (tid < N_) {
    const float* row = sd + tid*197;
    float rs = 0.f, best = -1.f;
    int bi = 0;
    for (int m = 0; m < N_; ++m) {
      const float v = row[m];
      rs += v;
      if (v > best) { best = v; bi = m; }
    }
    const float diag = row[tid];
    sl[tid] = logf(rs + (float)N_ * EPS_) - logf(diag + EPS_);
    sa[tid] = (bi == tid) ? 1.f : 0.f;
  }
  __syncthreads();
  if (tid == 0) {
    float L = 0.f, A = 0.f;
    for (int i = 0; i < N_; ++i) { L += sl[i]; A += sa[i]; }
    g_partial[b]      = L;
    g_partial[B_ + b] = A;
  }
}

__global__ void kE(float* out, int out_size) {
  float L = 0.f, A = 0.f;
  for (int b = 0; b < B_; ++b) { L += g_partial[b]; A += g_partial[B_ + b]; }
  const float inv = 1.0f / (float)(B_ * N_);
  if (out_size > QSIZE)     out[QSIZE]     = L * inv;
  if (out_size > QSIZE + 1) out[QSIZE + 1] = A * inv;
}

// =============================================================================
extern "C" void kernel_launch(void* const* d_in, const int* in_sizes, int n_in,
                              void* d_out, int out_size) {
  const float* maps = (const float*)d_in[0];
  const float* W    = (const float*)d_in[1];
  const float* bias = (const float*)d_in[2];
  float* out = (float*)d_out;

  cudaFuncSetAttribute(kP, cudaFuncAttributeMaxDynamicSharedMemorySize, (int)SMEM_P_BYTES);
  cudaFuncSetAttribute(kG, cudaFuncAttributeMaxDynamicSharedMemorySize, (int)SMEM_G_BYTES);
  cudaFuncSetAttribute(kQ, cudaFuncAttributeMaxDynamicSharedMemorySize, (int)SMEM_Q_BYTES);
  cudaFuncSetAttribute(kB, cudaFuncAttributeMaxDynamicSharedMemorySize, (int)SMEM_B2_BYTES);
  cudaFuncSetAttribute(kT, cudaFuncAttributeMaxDynamicSharedMemorySize, (int)SMEM_T_BYTES);
  cudaFuncSetAttribute(kD, cudaFuncAttributeMaxDynamicSharedMemorySize, (int)SMEM_D_BYTES);

  kP<<<B_*N_, 256, SMEM_P_BYTES>>>(maps);
  kW<<<256, 256>>>(W);
  kG<<<M_/128, 256, SMEM_G_BYTES>>>(bias);
  kB<<<dim3(T_ - 1, B_), 448, SMEM_B2_BYTES>>>();
  kQ<<<dim3(T_, B_), 256, SMEM_Q_BYTES>>>(out);

  // triple-product tree: 38 -> 13 -> 5 -> 2 -> 1
  kT<<<dim3(2, 13, B_), 224, SMEM_T_BYTES>>>(0, 38);
  kT<<<dim3(2,  5, B_), 224, SMEM_T_BYTES>>>(1, 13);
  kT<<<dim3(2,  2, B_), 224, SMEM_T_BYTES>>>(2,  5);
  kT<<<dim3(2,  1, B_), 224, SMEM_T_BYTES>>>(3,  2);

  kD<<<B_, 224, SMEM_D_BYTES>>>();
  kE<<<1, 1>>>(out, out_size);
}